// round 11
// baseline (speedup 1.0000x reference)
#include <cuda_runtime.h>
#include <cuda_fp16.h>
#include <stdint.h>
#include <math.h>

#define CC 256
#define NT 4096
#define BB 8
#define TQ 128         // queries per CTA
#define TK 64          // keys per tile
#define QSTR 264       // half stride of Q/K/V SMEM rows (528B)
#define PSTR 72        // half stride of P buffer (144B)
#define SXSTR 68       // float stride of S exchange buffer

// Q pre-scale folds softmax scale (1/16) and log2(e) so P = exp2(S_mma)
#define QSCALE 0.0901684403f

// fp16 scratch, all [b][n][c]
__device__ __half g_q[(size_t)BB * NT * CC];
__device__ __half g_k[(size_t)BB * NT * CC];
__device__ __half g_v[(size_t)BB * NT * CC];

// attn SMEM byte offsets
#define SM_Q   0u          // 128 x 264 fp16 = 67584
#define SM_K   67584u      // 64 x 264 fp16  = 33792
#define SM_V   101376u     // 2 slots x 64 x 264 fp16 = 67584
#define VSLOT  33792u
#define SM_SX  168960u     // fp32 [128][68] = 34816
#define SM_P   203776u     // fp16 [128][72] = 18432
#define SM_PS  222208u     // float[4][128] = 2048
#define SMEM_BYTES 224256u

// qkv SMEM: Ws [256][264] fp16 = 135168, Xs [256][136] fp16 = 69632
#define QK_WS   0u
#define QK_XS   135168u
#define QK_SMEM 204800u

__device__ __forceinline__ uint32_t smem_u32(const void* p) {
    uint32_t a;
    asm("{ .reg .u64 t; cvta.to.shared.u64 t, %1; cvt.u32.u64 %0, t; }" : "=r"(a) : "l"(p));
    return a;
}
__device__ __forceinline__ float ex2(float x) {
    float y; asm("ex2.approx.ftz.f32 %0, %1;" : "=f"(y) : "f"(x)); return y;
}
__device__ __forceinline__ void ldsm_x4(uint32_t* r, uint32_t a) {
    asm volatile("ldmatrix.sync.aligned.m8n8.x4.shared.b16 {%0,%1,%2,%3}, [%4];"
        : "=r"(r[0]), "=r"(r[1]), "=r"(r[2]), "=r"(r[3]) : "r"(a));
}
__device__ __forceinline__ void ldsm_x4_t(uint32_t* r, uint32_t a) {
    asm volatile("ldmatrix.sync.aligned.m8n8.x4.trans.shared.b16 {%0,%1,%2,%3}, [%4];"
        : "=r"(r[0]), "=r"(r[1]), "=r"(r[2]), "=r"(r[3]) : "r"(a));
}
__device__ __forceinline__ void mma16816(float* c, const uint32_t* a, const uint32_t* b) {
    asm volatile("mma.sync.aligned.m16n8k16.row.col.f32.f16.f16.f32 "
        "{%0,%1,%2,%3}, {%4,%5,%6,%7}, {%8,%9}, {%0,%1,%2,%3};"
        : "+f"(c[0]), "+f"(c[1]), "+f"(c[2]), "+f"(c[3])
        : "r"(a[0]), "r"(a[1]), "r"(a[2]), "r"(a[3]), "r"(b[0]), "r"(b[1]));
}
__device__ __forceinline__ void cpa16(uint32_t s, const void* g) {
    asm volatile("cp.async.cg.shared.global [%0], [%1], 16;" :: "r"(s), "l"(g));
}
#define CPA_COMMIT() asm volatile("cp.async.commit_group;" ::: "memory")
#define CPA_WAIT0()  asm volatile("cp.async.wait_group 0;" ::: "memory")

// ---------------------------------------------------------------------------
// QKV projection via HMMA: 128 tokens per CTA.
//   A = W[d][c] (ldsm, stride 264), B = X[c][n] (ldsm trans, stride 136)
//   warp (dg, tg): d rows dg*64..+64, tokens tg*64..+64
// ---------------------------------------------------------------------------
__global__ __launch_bounds__(256, 1) void qkv_kernel(
    const float* __restrict__ x, const float* __restrict__ mo,
    const float* __restrict__ wq, const float* __restrict__ bq,
    const float* __restrict__ wk, const float* __restrict__ bk,
    const float* __restrict__ wv, const float* __restrict__ bv)
{
    extern __shared__ __align__(16) char smem[];
    const uint32_t sbase = smem_u32(smem);
    __half* Ws = (__half*)(smem + QK_WS);
    __half* Xs = (__half*)(smem + QK_XS);

    const int which = blockIdx.z % 3;
    const int b = blockIdx.z / 3;
    const float* X; const float* W; const float* bias; __half* out; float sc;
    if (which == 0)      { X = x;  W = wq; bias = bq; out = g_q; sc = QSCALE; }
    else if (which == 1) { X = mo; W = wk; bias = bk; out = g_k; sc = 1.0f; }
    else                 { X = mo; W = wv; bias = bv; out = g_v; sc = 1.0f; }
    X   += (size_t)b * CC * NT;
    out += (size_t)b * NT * CC;

    const int n0 = blockIdx.x * 128;
    const int t = threadIdx.x;
    const int warp = t >> 5, lane = t & 31;
    const int dg = warp >> 1, tg = warp & 1;
    const int g = lane >> 2, t4 = lane & 3, l16 = lane & 15;

    // W [256][256] fp32 -> fp16 stride 264
    for (int idx = t; idx < 16384; idx += 256) {
        const int row = idx >> 6, c4 = idx & 63;
        float4 w4 = *(const float4*)&W[(size_t)row * CC + c4 * 4];
        __half2 h0 = __floats2half2_rn(w4.x, w4.y);
        __half2 h1 = __floats2half2_rn(w4.z, w4.w);
        uint2 u; u.x = *(uint32_t*)&h0; u.y = *(uint32_t*)&h1;
        *(uint2*)&Ws[row * 264 + c4 * 4] = u;
    }
    // X tile [256 c][128 n] fp32 -> fp16 stride 136
    for (int idx = t; idx < 8192; idx += 256) {
        const int row = idx >> 5, n4 = idx & 31;
        float4 x4 = *(const float4*)&X[(size_t)row * NT + n0 + n4 * 4];
        __half2 h0 = __floats2half2_rn(x4.x, x4.y);
        __half2 h1 = __floats2half2_rn(x4.z, x4.w);
        uint2 u; u.x = *(uint32_t*)&h0; u.y = *(uint32_t*)&h1;
        *(uint2*)&Xs[row * 136 + n4 * 4] = u;
    }
    __syncthreads();

    float oacc[4][8][4];   // [qm][nb]: d = dg*64+qm*16+{g,g+8}, tok = tg*64+nb*8+2t4
    #pragma unroll
    for (int qm = 0; qm < 4; qm++)
        #pragma unroll
        for (int nb = 0; nb < 8; nb++)
            #pragma unroll
            for (int e = 0; e < 4; e++) oacc[qm][nb][e] = 0.f;

    #pragma unroll
    for (int ks2 = 0; ks2 < 16; ks2++) {
        uint32_t aW[4][4];
        #pragma unroll
        for (int qm = 0; qm < 4; qm++)
            ldsm_x4(aW[qm], sbase + QK_WS +
                    (uint32_t)(((dg * 64 + qm * 16 + l16) * 264 +
                                ks2 * 16 + (lane >> 4) * 8) * 2));
        #pragma unroll
        for (int pair = 0; pair < 4; pair++) {
            uint32_t bf[4];
            ldsm_x4_t(bf, sbase + QK_XS +
                      (uint32_t)(((ks2 * 16 + l16) * 136 +
                                  tg * 64 + pair * 16 + (lane >> 4) * 8) * 2));
            #pragma unroll
            for (int qm = 0; qm < 4; qm++) {
                mma16816(oacc[qm][pair * 2],     aW[qm], bf);
                mma16816(oacc[qm][pair * 2 + 1], aW[qm], bf + 2);
            }
        }
    }
    __syncthreads();   // Ws reads done before sf overlay

    // epilogue: bias+scale, fp16, transpose-stage sf[tok][264], store [n][c]
    {
        __half* sf = (__half*)smem;  // [128][264]
        #pragma unroll
        for (int qm = 0; qm < 4; qm++) {
            const int d0 = dg * 64 + qm * 16 + g, d1 = d0 + 8;
            const float b0 = bias[d0], b1 = bias[d1];
            #pragma unroll
            for (int nb = 0; nb < 8; nb++) {
                const int tok = tg * 64 + nb * 8 + t4 * 2;
                sf[tok * 264 + d0]       = __float2half_rn((oacc[qm][nb][0] + b0) * sc);
                sf[(tok + 1) * 264 + d0] = __float2half_rn((oacc[qm][nb][1] + b0) * sc);
                sf[tok * 264 + d1]       = __float2half_rn((oacc[qm][nb][2] + b1) * sc);
                sf[(tok + 1) * 264 + d1] = __float2half_rn((oacc[qm][nb][3] + b1) * sc);
            }
        }
        __syncthreads();
        const int row = t >> 1, seg = (t & 1) * 128;
        #pragma unroll
        for (int i = 0; i < 16; i++)
            *(uint4*)&out[(size_t)(n0 + row) * CC + seg + i * 8] =
                *(uint4*)&sf[row * 264 + seg + i * 8];
    }
}

// ---------------------------------------------------------------------------
// attn cp.async helpers (512 threads)
// ---------------------------------------------------------------------------
__device__ __forceinline__ void cpa_k(uint32_t sbase, const __half* kb, int k0, int t) {
    const int row = t >> 3, c8 = t & 7;
    const __half* src = kb + (size_t)(k0 + row) * CC + c8 * 32;
    uint32_t dst = sbase + SM_K + (uint32_t)(row * QSTR + c8 * 32) * 2;
    #pragma unroll
    for (int i = 0; i < 4; i++) cpa16(dst + i * 16, src + i * 8);
}
__device__ __forceinline__ void cpa_v(uint32_t sbase, const __half* vb, int row0, int slot, int t) {
    const int row = t >> 3, c8 = t & 7;
    const __half* src = vb + (size_t)(row0 + row) * CC + c8 * 32;
    uint32_t dst = sbase + SM_V + (uint32_t)slot * VSLOT + (uint32_t)(row * QSTR + c8 * 32) * 2;
    #pragma unroll
    for (int i = 0; i < 4; i++) cpa16(dst + i * 16, src + i * 8);
}

// ---------------------------------------------------------------------------
// HMMA flash attention (fixed-max softmax), 512 threads, 128 q/CTA, 64-key tiles.
//   S phase:  warp (qg, kg, cs): rows qg*32..+32, keys kg*32..+32, ch cs*128..+128
//     symmetric exchange: publish partials for the other half's 16 cols,
//     own 16 cols -> combine + exp2 + P write (all 16 warps do equal work)
//   PV phase: warp (qh, cg): rows qh*64..+64, channels cg*32..+32
// ---------------------------------------------------------------------------
__global__ __launch_bounds__(512, 1) void attn_kernel(float* __restrict__ gout)
{
    extern __shared__ __align__(16) char smem[];
    const uint32_t sbase = smem_u32(smem);
    float* Sx   = (float*)(smem + SM_SX);   // [128][68]
    float* psum = (float*)(smem + SM_PS);   // [4][128]

    const int t = threadIdx.x;
    const int warp = t >> 5, lane = t & 31;
    const int qg = warp >> 2;               // 0..3
    const int kg = (warp >> 1) & 1;         // 0..1
    const int cs = warp & 1;                // 0..1 channel half
    const int qh = warp >> 3;               // PV row half
    const int cg = warp & 7;                // PV channel group
    const int g = lane >> 2, t4 = lane & 3, l16 = lane & 15;
    const int qb = qg * 32, cb = kg * 32;
    const int oq = qh * 64, cw = cg * 32;

    const int b = blockIdx.y;
    const int i0 = blockIdx.x * TQ;

    const __half* kbase = g_k + (size_t)b * NT * CC;
    const __half* vbase = g_v + (size_t)b * NT * CC;

    cpa_k(sbase, kbase, 0, t);
    cpa_v(sbase, vbase, 0, 0, t);
    CPA_COMMIT();
    {
        const int row = t >> 2, quarter = t & 3;
        const __half* src = g_q + ((size_t)b * NT + i0 + row) * CC + quarter * 64;
        __half* dst = (__half*)(smem + SM_Q) + row * QSTR + quarter * 64;
        #pragma unroll
        for (int i = 0; i < 8; i++)
            *(uint4*)(dst + i * 8) = *(const uint4*)(src + i * 8);
    }
    CPA_WAIT0();
    __syncthreads();

    float oacc[4][4][4];
    #pragma unroll
    for (int qm = 0; qm < 4; qm++)
        #pragma unroll
        for (int nb = 0; nb < 4; nb++)
            #pragma unroll
            for (int e = 0; e < 4; e++) oacc[qm][nb][e] = 0.f;

    float suml[2][2] = {};   // per warp: owned 16 cols; [qm][g-half]

    for (int kt = 0; kt < NT / TK; kt++) {
        // ---- S partial: 32q x 32k over this warp's 128 channels ----
        float sacc[2][4][4];
        #pragma unroll
        for (int qm = 0; qm < 2; qm++)
            #pragma unroll
            for (int nb = 0; nb < 4; nb++)
                #pragma unroll
                for (int e = 0; e < 4; e++) sacc[qm][nb][e] = 0.f;

        #pragma unroll
        for (int ks2 = 0; ks2 < 8; ks2++) {
            const int ck = cs * 8 + ks2;
            uint32_t a[2][4];
            #pragma unroll
            for (int qm = 0; qm < 2; qm++)
                ldsm_x4(a[qm], sbase + SM_Q +
                        (uint32_t)(((qb + qm * 16 + l16) * QSTR +
                                    ck * 16 + (lane >> 4) * 8) * 2));
            #pragma unroll
            for (int pair = 0; pair < 2; pair++) {
                uint32_t bf[4];
                ldsm_x4(bf, sbase + SM_K +
                        (uint32_t)(((cb + pair * 16 + (lane >> 4) * 8 + (lane & 7)) * QSTR +
                                    ck * 16 + ((lane >> 3) & 1) * 8) * 2));
                #pragma unroll
                for (int qm = 0; qm < 2; qm++) {
                    mma16816(sacc[qm][pair * 2],     a[qm], bf);
                    mma16816(sacc[qm][pair * 2 + 1], a[qm], bf + 2);
                }
            }
        }

        // publish partials for the other half's columns (float2)
        {
            const int nbp = (1 - cs) * 2;
            #pragma unroll
            for (int qm = 0; qm < 2; qm++) {
                const int ra = qb + qm * 16 + g, rb = ra + 8;
                #pragma unroll
                for (int k2 = 0; k2 < 2; k2++) {
                    const int nb = nbp + k2;
                    const int col = cb + nb * 8 + t4 * 2;
                    *(float2*)&Sx[ra * SXSTR + col] =
                        make_float2(sacc[qm][nb][0], sacc[qm][nb][1]);
                    *(float2*)&Sx[rb * SXSTR + col] =
                        make_float2(sacc[qm][nb][2], sacc[qm][nb][3]);
                }
            }
        }
        __syncthreads();   // #1: Sx ready; S reads of K done

        const int last = (kt == NT / TK - 1);
        if (!last) {
            cpa_k(sbase, kbase, (kt + 1) * TK, t);
            cpa_v(sbase, vbase, (kt + 1) * TK, (kt + 1) & 1, t);
        }
        CPA_COMMIT();

        // all warps: combine owned 16 cols, exp2, write P, accumulate sums
        {
            __half* P = (__half*)(smem + SM_P);
            const int nbo = cs * 2;
            #pragma unroll
            for (int qm = 0; qm < 2; qm++) {
                const int ra = qb + qm * 16 + g, rb = ra + 8;
                #pragma unroll
                for (int k2 = 0; k2 < 2; k2++) {
                    const int nb = nbo + k2;
                    const int col = cb + nb * 8 + t4 * 2;
                    float2 xa = *(float2*)&Sx[ra * SXSTR + col];
                    float2 xb = *(float2*)&Sx[rb * SXSTR + col];
                    const float e00 = ex2(sacc[qm][nb][0] + xa.x);
                    const float e01 = ex2(sacc[qm][nb][1] + xa.y);
                    const float e10 = ex2(sacc[qm][nb][2] + xb.x);
                    const float e11 = ex2(sacc[qm][nb][3] + xb.y);
                    suml[qm][0] += e00 + e01; suml[qm][1] += e10 + e11;
                    *(__half2*)(P + ra * PSTR + col) = __floats2half2_rn(e00, e01);
                    *(__half2*)(P + rb * PSTR + col) = __floats2half2_rn(e10, e11);
                }
            }
        }
        __syncthreads();   // #2: P ready

        // ---- PV: O[128 q][32 c per warp] += P[128][64] V[64][32] ----
        const uint32_t vS = sbase + SM_V + (uint32_t)(kt & 1) * VSLOT;
        #pragma unroll
        for (int ks2 = 0; ks2 < 4; ks2++) {
            uint32_t aP[4][4];
            #pragma unroll
            for (int qm = 0; qm < 4; qm++)
                ldsm_x4(aP[qm], sbase + SM_P +
                        (uint32_t)(((oq + qm * 16 + l16) * PSTR +
                                    ks2 * 16 + (lane >> 4) * 8) * 2));
            #pragma unroll
            for (int pair = 0; pair < 2; pair++) {
                uint32_t bf[4];
                ldsm_x4_t(bf, vS + (uint32_t)(((ks2 * 16 + l16) * QSTR +
                                               cw + pair * 16 + (lane >> 4) * 8) * 2));
                #pragma unroll
                for (int qm = 0; qm < 4; qm++) {
                    mma16816(oacc[qm][pair * 2],     aP[qm], bf);
                    mma16816(oacc[qm][pair * 2 + 1], aP[qm], bf + 2);
                }
            }
        }
        CPA_WAIT0();
        __syncthreads();   // #3: next K/V landed; P, Sx free
    }

    // final row-sum reduction: 4 partials per row, indexed (kg*2+cs)
    #pragma unroll
    for (int qm = 0; qm < 2; qm++)
        #pragma unroll
        for (int h = 0; h < 2; h++) {
            suml[qm][h] += __shfl_xor_sync(0xffffffffu, suml[qm][h], 1);
            suml[qm][h] += __shfl_xor_sync(0xffffffffu, suml[qm][h], 2);
        }
    if (t4 == 0) {
        const int part = kg * 2 + cs;
        #pragma unroll
        for (int qm = 0; qm < 2; qm++) {
            psum[part * 128 + qb + qm * 16 + g]     = suml[qm][0];
            psum[part * 128 + qb + qm * 16 + g + 8] = suml[qm][1];
        }
    }
    __syncthreads();

    // normalize + stage O^T [c][q] (fp32 [256][132]), coalesced store
    {
        float* sf = (float*)smem;
        float inv0[4], inv1[4];
        #pragma unroll
        for (int qm = 0; qm < 4; qm++) {
            const int ra = oq + qm * 16 + g, rb = ra + 8;
            inv0[qm] = 1.f / (psum[ra] + psum[128 + ra] + psum[256 + ra] + psum[384 + ra]);
            inv1[qm] = 1.f / (psum[rb] + psum[128 + rb] + psum[256 + rb] + psum[384 + rb]);
        }
        __syncthreads();
        #pragma unroll
        for (int qm = 0; qm < 4; qm++) {
            const int ra = oq + qm * 16 + g, rb = ra + 8;
            #pragma unroll
            for (int nb = 0; nb < 4; nb++) {
                const int col = cw + nb * 8 + t4 * 2;
                sf[col * 132 + ra]       = oacc[qm][nb][0] * inv0[qm];
                sf[(col + 1) * 132 + ra] = oacc[qm][nb][1] * inv0[qm];
                sf[col * 132 + rb]       = oacc[qm][nb][2] * inv1[qm];
                sf[(col + 1) * 132 + rb] = oacc[qm][nb][3] * inv1[qm];
            }
        }
        __syncthreads();
        float* obase = gout + (size_t)b * CC * NT + i0;
        #pragma unroll
        for (int pass = 0; pass < 2; pass++) {
            const int c = (t >> 2) + pass * 128;
            const int q0 = (t & 3) * 32;
            #pragma unroll
            for (int i = 0; i < 8; i++)
                *(float4*)&obase[(size_t)c * NT + q0 + i * 4] =
                    *(float4*)&sf[c * 132 + q0 + i * 4];
        }
    }
}

extern "C" void kernel_launch(void* const* d_in, const int* in_sizes, int n_in,
                              void* d_out, int out_size)
{
    const float* x  = (const float*)d_in[0];
    const float* mo = (const float*)d_in[1];
    const float* wq = (const float*)d_in[2];
    const float* bq = (const float*)d_in[3];
    const float* wk = (const float*)d_in[4];
    const float* bk = (const float*)d_in[5];
    const float* wv = (const float*)d_in[6];
    const float* bv = (const float*)d_in[7];
    float* out = (float*)d_out;

    cudaFuncSetAttribute(qkv_kernel, cudaFuncAttributeMaxDynamicSharedMemorySize,
                         (int)QK_SMEM);
    dim3 g1(NT / 128, 1, BB * 3);
    qkv_kernel<<<g1, 256, QK_SMEM>>>(x, mo, wq, bq, wk, bk, wv, bv);

    cudaFuncSetAttribute(attn_kernel, cudaFuncAttributeMaxDynamicSharedMemorySize,
                         (int)SMEM_BYTES);
    dim3 g2(NT / TQ, BB);
    attn_kernel<<<g2, 512, SMEM_BYTES>>>(out);
}

// round 12
// speedup vs baseline: 1.1897x; 1.1897x over previous
#include <cuda_runtime.h>
#include <cuda_fp16.h>
#include <stdint.h>
#include <math.h>

#define CC 256
#define NT 4096
#define BB 8
#define TQ 128         // queries per CTA
#define TK 64          // keys per tile
#define QSTR 264       // half stride of Q/K/V SMEM rows (528B)
#define PSTR 72        // half stride of P buffer (144B)
#define SXSTR 68       // float stride of S exchange buffer

// Q pre-scale folds softmax scale (1/16) and log2(e) so P = exp2(S_mma)
#define QSCALE 0.0901684403f

// fp16 scratch, all [b][n][c]
__device__ __half g_q[(size_t)BB * NT * CC];
__device__ __half g_k[(size_t)BB * NT * CC];
__device__ __half g_v[(size_t)BB * NT * CC];

// attn SMEM byte offsets
#define SM_Q   0u          // 128 x 264 fp16 = 67584
#define SM_K   67584u      // 64 x 264 fp16  = 33792
#define SM_V   101376u     // 2 slots x 64 x 264 fp16 = 67584
#define VSLOT  33792u
#define SM_SX  168960u     // fp32 [128][68] = 34816
#define SM_P   203776u     // fp16 [128][72] = 18432
#define SM_PS  222208u     // float[2][128]
#define SMEM_BYTES 223232u

// qkv SMEM: Ws [256][264] fp16 = 135168, Xs [256][136] fp16 = 69632
#define QK_WS   0u
#define QK_XS   135168u
#define QK_SMEM 204800u

__device__ __forceinline__ uint32_t smem_u32(const void* p) {
    uint32_t a;
    asm("{ .reg .u64 t; cvta.to.shared.u64 t, %1; cvt.u32.u64 %0, t; }" : "=r"(a) : "l"(p));
    return a;
}
__device__ __forceinline__ float ex2(float x) {
    float y; asm("ex2.approx.ftz.f32 %0, %1;" : "=f"(y) : "f"(x)); return y;
}
__device__ __forceinline__ void ldsm_x4(uint32_t* r, uint32_t a) {
    asm volatile("ldmatrix.sync.aligned.m8n8.x4.shared.b16 {%0,%1,%2,%3}, [%4];"
        : "=r"(r[0]), "=r"(r[1]), "=r"(r[2]), "=r"(r[3]) : "r"(a));
}
__device__ __forceinline__ void ldsm_x4_t(uint32_t* r, uint32_t a) {
    asm volatile("ldmatrix.sync.aligned.m8n8.x4.trans.shared.b16 {%0,%1,%2,%3}, [%4];"
        : "=r"(r[0]), "=r"(r[1]), "=r"(r[2]), "=r"(r[3]) : "r"(a));
}
__device__ __forceinline__ void mma16816(float* c, const uint32_t* a, const uint32_t* b) {
    asm volatile("mma.sync.aligned.m16n8k16.row.col.f32.f16.f16.f32 "
        "{%0,%1,%2,%3}, {%4,%5,%6,%7}, {%8,%9}, {%0,%1,%2,%3};"
        : "+f"(c[0]), "+f"(c[1]), "+f"(c[2]), "+f"(c[3])
        : "r"(a[0]), "r"(a[1]), "r"(a[2]), "r"(a[3]), "r"(b[0]), "r"(b[1]));
}
__device__ __forceinline__ void cpa16(uint32_t s, const void* g) {
    asm volatile("cp.async.cg.shared.global [%0], [%1], 16;" :: "r"(s), "l"(g));
}
#define CPA_COMMIT() asm volatile("cp.async.commit_group;" ::: "memory")
#define CPA_WAIT0()  asm volatile("cp.async.wait_group 0;" ::: "memory")

// ---------------------------------------------------------------------------
// QKV projection via HMMA: 128 tokens per CTA (R11 version — measured win).
// ---------------------------------------------------------------------------
__global__ __launch_bounds__(256, 1) void qkv_kernel(
    const float* __restrict__ x, const float* __restrict__ mo,
    const float* __restrict__ wq, const float* __restrict__ bq,
    const float* __restrict__ wk, const float* __restrict__ bk,
    const float* __restrict__ wv, const float* __restrict__ bv)
{
    extern __shared__ __align__(16) char smem[];
    const uint32_t sbase = smem_u32(smem);
    __half* Ws = (__half*)(smem + QK_WS);
    __half* Xs = (__half*)(smem + QK_XS);

    const int which = blockIdx.z % 3;
    const int b = blockIdx.z / 3;
    const float* X; const float* W; const float* bias; __half* out; float sc;
    if (which == 0)      { X = x;  W = wq; bias = bq; out = g_q; sc = QSCALE; }
    else if (which == 1) { X = mo; W = wk; bias = bk; out = g_k; sc = 1.0f; }
    else                 { X = mo; W = wv; bias = bv; out = g_v; sc = 1.0f; }
    X   += (size_t)b * CC * NT;
    out += (size_t)b * NT * CC;

    const int n0 = blockIdx.x * 128;
    const int t = threadIdx.x;
    const int warp = t >> 5, lane = t & 31;
    const int dg = warp >> 1, tg = warp & 1;
    const int g = lane >> 2, t4 = lane & 3, l16 = lane & 15;

    for (int idx = t; idx < 16384; idx += 256) {
        const int row = idx >> 6, c4 = idx & 63;
        float4 w4 = *(const float4*)&W[(size_t)row * CC + c4 * 4];
        __half2 h0 = __floats2half2_rn(w4.x, w4.y);
        __half2 h1 = __floats2half2_rn(w4.z, w4.w);
        uint2 u; u.x = *(uint32_t*)&h0; u.y = *(uint32_t*)&h1;
        *(uint2*)&Ws[row * 264 + c4 * 4] = u;
    }
    for (int idx = t; idx < 8192; idx += 256) {
        const int row = idx >> 5, n4 = idx & 31;
        float4 x4 = *(const float4*)&X[(size_t)row * NT + n0 + n4 * 4];
        __half2 h0 = __floats2half2_rn(x4.x, x4.y);
        __half2 h1 = __floats2half2_rn(x4.z, x4.w);
        uint2 u; u.x = *(uint32_t*)&h0; u.y = *(uint32_t*)&h1;
        *(uint2*)&Xs[row * 136 + n4 * 4] = u;
    }
    __syncthreads();

    float oacc[4][8][4];
    #pragma unroll
    for (int qm = 0; qm < 4; qm++)
        #pragma unroll
        for (int nb = 0; nb < 8; nb++)
            #pragma unroll
            for (int e = 0; e < 4; e++) oacc[qm][nb][e] = 0.f;

    #pragma unroll
    for (int ks2 = 0; ks2 < 16; ks2++) {
        uint32_t aW[4][4];
        #pragma unroll
        for (int qm = 0; qm < 4; qm++)
            ldsm_x4(aW[qm], sbase + QK_WS +
                    (uint32_t)(((dg * 64 + qm * 16 + l16) * 264 +
                                ks2 * 16 + (lane >> 4) * 8) * 2));
        #pragma unroll
        for (int pair = 0; pair < 4; pair++) {
            uint32_t bf[4];
            ldsm_x4_t(bf, sbase + QK_XS +
                      (uint32_t)(((ks2 * 16 + l16) * 136 +
                                  tg * 64 + pair * 16 + (lane >> 4) * 8) * 2));
            #pragma unroll
            for (int qm = 0; qm < 4; qm++) {
                mma16816(oacc[qm][pair * 2],     aW[qm], bf);
                mma16816(oacc[qm][pair * 2 + 1], aW[qm], bf + 2);
            }
        }
    }
    __syncthreads();

    {
        __half* sf = (__half*)smem;  // [128][264]
        #pragma unroll
        for (int qm = 0; qm < 4; qm++) {
            const int d0 = dg * 64 + qm * 16 + g, d1 = d0 + 8;
            const float b0 = bias[d0], b1 = bias[d1];
            #pragma unroll
            for (int nb = 0; nb < 8; nb++) {
                const int tok = tg * 64 + nb * 8 + t4 * 2;
                sf[tok * 264 + d0]       = __float2half_rn((oacc[qm][nb][0] + b0) * sc);
                sf[(tok + 1) * 264 + d0] = __float2half_rn((oacc[qm][nb][1] + b0) * sc);
                sf[tok * 264 + d1]       = __float2half_rn((oacc[qm][nb][2] + b1) * sc);
                sf[(tok + 1) * 264 + d1] = __float2half_rn((oacc[qm][nb][3] + b1) * sc);
            }
        }
        __syncthreads();
        const int row = t >> 1, seg = (t & 1) * 128;
        #pragma unroll
        for (int i = 0; i < 16; i++)
            *(uint4*)&out[(size_t)(n0 + row) * CC + seg + i * 8] =
                *(uint4*)&sf[row * 264 + seg + i * 8];
    }
}

// ---------------------------------------------------------------------------
// attn cp.async helpers (512 threads)
// ---------------------------------------------------------------------------
__device__ __forceinline__ void cpa_k(uint32_t sbase, const __half* kb, int k0, int t) {
    const int row = t >> 3, c8 = t & 7;
    const __half* src = kb + (size_t)(k0 + row) * CC + c8 * 32;
    uint32_t dst = sbase + SM_K + (uint32_t)(row * QSTR + c8 * 32) * 2;
    #pragma unroll
    for (int i = 0; i < 4; i++) cpa16(dst + i * 16, src + i * 8);
}
__device__ __forceinline__ void cpa_v(uint32_t sbase, const __half* vb, int row0, int slot, int t) {
    const int row = t >> 3, c8 = t & 7;
    const __half* src = vb + (size_t)(row0 + row) * CC + c8 * 32;
    uint32_t dst = sbase + SM_V + (uint32_t)slot * VSLOT + (uint32_t)(row * QSTR + c8 * 32) * 2;
    #pragma unroll
    for (int i = 0; i < 4; i++) cpa16(dst + i * 16, src + i * 8);
}

// ---------------------------------------------------------------------------
// HMMA flash attention — exact R10 structure (best measured: 638 us).
//   S phase:  warp (qg, kg, cs): rows qg*32..+32, keys kg*32..+32, ch cs*128..+128
//             cs=1 writes partials to Sx; cs=0 adds, exp2, writes P.
//   PV phase: warp (qh, cg): rows qh*64..+64, channels cg*32..+32
// ---------------------------------------------------------------------------
__global__ __launch_bounds__(512, 1) void attn_kernel(float* __restrict__ gout)
{
    extern __shared__ __align__(16) char smem[];
    const uint32_t sbase = smem_u32(smem);
    float* Sx   = (float*)(smem + SM_SX);   // [128][68]
    float* psum = (float*)(smem + SM_PS);   // [2][128]

    const int t = threadIdx.x;
    const int warp = t >> 5, lane = t & 31;
    const int qg = warp >> 2;               // 0..3
    const int kg = (warp >> 1) & 1;         // 0..1
    const int cs = warp & 1;                // 0..1 channel half
    const int qh = warp >> 3;               // PV row half
    const int cg = warp & 7;                // PV channel group
    const int g = lane >> 2, t4 = lane & 3, l16 = lane & 15;
    const int qb = qg * 32, cb = kg * 32;
    const int oq = qh * 64, cw = cg * 32;

    const int b = blockIdx.y;
    const int i0 = blockIdx.x * TQ;

    const __half* kbase = g_k + (size_t)b * NT * CC;
    const __half* vbase = g_v + (size_t)b * NT * CC;

    cpa_k(sbase, kbase, 0, t);
    cpa_v(sbase, vbase, 0, 0, t);
    CPA_COMMIT();
    {
        const int row = t >> 2, quarter = t & 3;
        const __half* src = g_q + ((size_t)b * NT + i0 + row) * CC + quarter * 64;
        __half* dst = (__half*)(smem + SM_Q) + row * QSTR + quarter * 64;
        #pragma unroll
        for (int i = 0; i < 8; i++)
            *(uint4*)(dst + i * 8) = *(const uint4*)(src + i * 8);
    }
    CPA_WAIT0();
    __syncthreads();

    float oacc[4][4][4];
    #pragma unroll
    for (int qm = 0; qm < 4; qm++)
        #pragma unroll
        for (int nb = 0; nb < 4; nb++)
            #pragma unroll
            for (int e = 0; e < 4; e++) oacc[qm][nb][e] = 0.f;

    float suml[2][2] = {};   // cs==0 warps only: [qm][g-half]

    for (int kt = 0; kt < NT / TK; kt++) {
        // ---- S partial: 32q x 32k over this warp's 128 channels ----
        float sacc[2][4][4];
        #pragma unroll
        for (int qm = 0; qm < 2; qm++)
            #pragma unroll
            for (int nb = 0; nb < 4; nb++)
                #pragma unroll
                for (int e = 0; e < 4; e++) sacc[qm][nb][e] = 0.f;

        #pragma unroll
        for (int ks2 = 0; ks2 < 8; ks2++) {
            const int ck = cs * 8 + ks2;
            uint32_t a[2][4];
            #pragma unroll
            for (int qm = 0; qm < 2; qm++)
                ldsm_x4(a[qm], sbase + SM_Q +
                        (uint32_t)(((qb + qm * 16 + l16) * QSTR +
                                    ck * 16 + (lane >> 4) * 8) * 2));
            #pragma unroll
            for (int pair = 0; pair < 2; pair++) {
                uint32_t bf[4];
                ldsm_x4(bf, sbase + SM_K +
                        (uint32_t)(((cb + pair * 16 + (lane >> 4) * 8 + (lane & 7)) * QSTR +
                                    ck * 16 + ((lane >> 3) & 1) * 8) * 2));
                #pragma unroll
                for (int qm = 0; qm < 2; qm++) {
                    mma16816(sacc[qm][pair * 2],     a[qm], bf);
                    mma16816(sacc[qm][pair * 2 + 1], a[qm], bf + 2);
                }
            }
        }

        // cs=1 warps publish partials
        if (cs) {
            #pragma unroll
            for (int qm = 0; qm < 2; qm++) {
                const int ra = qb + qm * 16 + g, rb = ra + 8;
                #pragma unroll
                for (int nb = 0; nb < 4; nb++) {
                    const int col = cb + nb * 8 + t4 * 2;
                    Sx[ra * SXSTR + col]     = sacc[qm][nb][0];
                    Sx[ra * SXSTR + col + 1] = sacc[qm][nb][1];
                    Sx[rb * SXSTR + col]     = sacc[qm][nb][2];
                    Sx[rb * SXSTR + col + 1] = sacc[qm][nb][3];
                }
            }
        }
        __syncthreads();   // #1: Sx ready; S reads of K done

        const int last = (kt == NT / TK - 1);
        if (!last) {
            cpa_k(sbase, kbase, (kt + 1) * TK, t);
            cpa_v(sbase, vbase, (kt + 1) * TK, (kt + 1) & 1, t);
        }
        CPA_COMMIT();

        // cs=0 warps: combine halves, exp2, write P, accumulate row sums
        if (!cs) {
            __half* P = (__half*)(smem + SM_P);
            #pragma unroll
            for (int qm = 0; qm < 2; qm++) {
                const int ra = qb + qm * 16 + g, rb = ra + 8;
                #pragma unroll
                for (int nb = 0; nb < 4; nb++) {
                    const int col = cb + nb * 8 + t4 * 2;
                    const float e00 = ex2(sacc[qm][nb][0] + Sx[ra * SXSTR + col]);
                    const float e01 = ex2(sacc[qm][nb][1] + Sx[ra * SXSTR + col + 1]);
                    const float e10 = ex2(sacc[qm][nb][2] + Sx[rb * SXSTR + col]);
                    const float e11 = ex2(sacc[qm][nb][3] + Sx[rb * SXSTR + col + 1]);
                    suml[qm][0] += e00 + e01; suml[qm][1] += e10 + e11;
                    *(__half2*)(P + ra * PSTR + col) = __floats2half2_rn(e00, e01);
                    *(__half2*)(P + rb * PSTR + col) = __floats2half2_rn(e10, e11);
                }
            }
        }
        __syncthreads();   // #2: P ready

        // ---- PV: O[128 q][32 c per warp] += P[128][64] V[64][32] ----
        const uint32_t vS = sbase + SM_V + (uint32_t)(kt & 1) * VSLOT;
        #pragma unroll
        for (int ks2 = 0; ks2 < 4; ks2++) {
            uint32_t aP[4][4];
            #pragma unroll
            for (int qm = 0; qm < 4; qm++)
                ldsm_x4(aP[qm], sbase + SM_P +
                        (uint32_t)(((oq + qm * 16 + l16) * PSTR +
                                    ks2 * 16 + (lane >> 4) * 8) * 2));
            #pragma unroll
            for (int pair = 0; pair < 2; pair++) {
                uint32_t bf[4];
                ldsm_x4_t(bf, vS + (uint32_t)(((ks2 * 16 + l16) * QSTR +
                                               cw + pair * 16 + (lane >> 4) * 8) * 2));
                #pragma unroll
                for (int qm = 0; qm < 4; qm++) {
                    mma16816(oacc[qm][pair * 2],     aP[qm], bf);
                    mma16816(oacc[qm][pair * 2 + 1], aP[qm], bf + 2);
                }
            }
        }
        CPA_WAIT0();
        __syncthreads();   // #3: next K/V landed; P, Sx free
    }

    // final row-sum reduction (cs==0 warps own [kg][rows])
    #pragma unroll
    for (int qm = 0; qm < 2; qm++)
        #pragma unroll
        for (int h = 0; h < 2; h++) {
            suml[qm][h] += __shfl_xor_sync(0xffffffffu, suml[qm][h], 1);
            suml[qm][h] += __shfl_xor_sync(0xffffffffu, suml[qm][h], 2);
        }
    if (!cs && t4 == 0) {
        #pragma unroll
        for (int qm = 0; qm < 2; qm++) {
            psum[kg * 128 + qb + qm * 16 + g]     = suml[qm][0];
            psum[kg * 128 + qb + qm * 16 + g + 8] = suml[qm][1];
        }
    }
    __syncthreads();

    // normalize + stage O^T [c][q] (fp32 [256][132]), coalesced store
    {
        float* sf = (float*)smem;
        float inv0[4], inv1[4];
        #pragma unroll
        for (int qm = 0; qm < 4; qm++) {
            const int ra = oq + qm * 16 + g, rb = ra + 8;
            inv0[qm] = 1.f / (psum[ra] + psum[128 + ra]);
            inv1[qm] = 1.f / (psum[rb] + psum[128 + rb]);
        }
        __syncthreads();
        #pragma unroll
        for (int qm = 0; qm < 4; qm++) {
            const int ra = oq + qm * 16 + g, rb = ra + 8;
            #pragma unroll
            for (int nb = 0; nb < 4; nb++) {
                const int col = cw + nb * 8 + t4 * 2;
                sf[col * 132 + ra]       = oacc[qm][nb][0] * inv0[qm];
                sf[(col + 1) * 132 + ra] = oacc[qm][nb][1] * inv0[qm];
                sf[col * 132 + rb]       = oacc[qm][nb][2] * inv1[qm];
                sf[(col + 1) * 132 + rb] = oacc[qm][nb][3] * inv1[qm];
            }
        }
        __syncthreads();
        float* obase = gout + (size_t)b * CC * NT + i0;
        #pragma unroll
        for (int pass = 0; pass < 2; pass++) {
            const int c = (t >> 2) + pass * 128;
            const int q0 = (t & 3) * 32;
            #pragma unroll
            for (int i = 0; i < 8; i++)
                *(float4*)&obase[(size_t)c * NT + q0 + i * 4] =
                    *(float4*)&sf[c * 132 + q0 + i * 4];
        }
    }
}

extern "C" void kernel_launch(void* const* d_in, const int* in_sizes, int n_in,
                              void* d_out, int out_size)
{
    const float* x  = (const float*)d_in[0];
    const float* mo = (const float*)d_in[1];
    const float* wq = (const float*)d_in[2];
    const float* bq = (const float*)d_in[3];
    const float* wk = (const float*)d_in[4];
    const float* bk = (const float*)d_in[5];
    const float* wv = (const float*)d_in[6];
    const float* bv = (const float*)d_in[7];
    float* out = (float*)d_out;

    cudaFuncSetAttribute(qkv_kernel, cudaFuncAttributeMaxDynamicSharedMemorySize,
                         (int)QK_SMEM);
    dim3 g1(NT / 128, 1, BB * 3);
    qkv_kernel<<<g1, 256, QK_SMEM>>>(x, mo, wq, bq, wk, bk, wv, bv);

    cudaFuncSetAttribute(attn_kernel, cudaFuncAttributeMaxDynamicSharedMemorySize,
                         (int)SMEM_BYTES);
    dim3 g2(NT / TQ, BB);
    attn_kernel<<<g2, 512, SMEM_BYTES>>>(out);
}

// round 13
// speedup vs baseline: 1.2832x; 1.0786x over previous
#include <cuda_runtime.h>
#include <cuda_fp16.h>
#include <stdint.h>
#include <math.h>

#define CC 256
#define NT 4096
#define BB 8
#define TQ 128         // queries per CTA (two independent 64-row halves)
#define TK 64          // keys per tile
#define QSTR 264       // half stride of Q/K/V SMEM rows (528B)
#define PSTR 72        // half stride of P / partial-exchange buffer (144B)

// Q pre-scale folds softmax scale (1/16) and log2(e) so P = exp2(S_mma)
#define QSCALE 0.0901684403f

// fp16 scratch, all [b][n][c]
__device__ __half g_q[(size_t)BB * NT * CC];
__device__ __half g_k[(size_t)BB * NT * CC];
__device__ __half g_v[(size_t)BB * NT * CC];

// attn SMEM byte offsets
#define SM_Q   0u          // 128 x 264 fp16 = 67584
#define SM_K   67584u      // 2 slots x 64 x 264 fp16 = 67584
#define KSLOT  33792u
#define SM_V   135168u     // 2 slots x 64 x 264 fp16 = 67584
#define VSLOT  33792u
#define SM_P   202752u     // fp16 [128][72] = 18432 (partials then P, in place)
#define SM_PS  221184u     // float[2][128] = 1024
#define SMEM_BYTES 222208u

// qkv SMEM: Ws [256][264] fp16 = 135168, Xs [256][136] fp16 = 69632
#define QK_WS   0u
#define QK_XS   135168u
#define QK_SMEM 204800u

__device__ __forceinline__ uint32_t smem_u32(const void* p) {
    uint32_t a;
    asm("{ .reg .u64 t; cvta.to.shared.u64 t, %1; cvt.u32.u64 %0, t; }" : "=r"(a) : "l"(p));
    return a;
}
__device__ __forceinline__ float ex2(float x) {
    float y; asm("ex2.approx.ftz.f32 %0, %1;" : "=f"(y) : "f"(x)); return y;
}
__device__ __forceinline__ void ldsm_x4(uint32_t* r, uint32_t a) {
    asm volatile("ldmatrix.sync.aligned.m8n8.x4.shared.b16 {%0,%1,%2,%3}, [%4];"
        : "=r"(r[0]), "=r"(r[1]), "=r"(r[2]), "=r"(r[3]) : "r"(a));
}
__device__ __forceinline__ void ldsm_x4_t(uint32_t* r, uint32_t a) {
    asm volatile("ldmatrix.sync.aligned.m8n8.x4.trans.shared.b16 {%0,%1,%2,%3}, [%4];"
        : "=r"(r[0]), "=r"(r[1]), "=r"(r[2]), "=r"(r[3]) : "r"(a));
}
__device__ __forceinline__ void mma16816(float* c, const uint32_t* a, const uint32_t* b) {
    asm volatile("mma.sync.aligned.m16n8k16.row.col.f32.f16.f16.f32 "
        "{%0,%1,%2,%3}, {%4,%5,%6,%7}, {%8,%9}, {%0,%1,%2,%3};"
        : "+f"(c[0]), "+f"(c[1]), "+f"(c[2]), "+f"(c[3])
        : "r"(a[0]), "r"(a[1]), "r"(a[2]), "r"(a[3]), "r"(b[0]), "r"(b[1]));
}
__device__ __forceinline__ void cpa16(uint32_t s, const void* g) {
    asm volatile("cp.async.cg.shared.global [%0], [%1], 16;" :: "r"(s), "l"(g));
}
#define CPA_COMMIT() asm volatile("cp.async.commit_group;" ::: "memory")
#define CPA_WAIT0()  asm volatile("cp.async.wait_group 0;" ::: "memory")
#define BAR_HALF(h)  asm volatile("bar.sync %0, 256;" :: "r"(1 + (h)) : "memory")

// ---------------------------------------------------------------------------
// QKV projection via HMMA: 128 tokens per CTA (R11/R12 version — measured).
// ---------------------------------------------------------------------------
__global__ __launch_bounds__(256, 1) void qkv_kernel(
    const float* __restrict__ x, const float* __restrict__ mo,
    const float* __restrict__ wq, const float* __restrict__ bq,
    const float* __restrict__ wk, const float* __restrict__ bk,
    const float* __restrict__ wv, const float* __restrict__ bv)
{
    extern __shared__ __align__(16) char smem[];
    const uint32_t sbase = smem_u32(smem);
    __half* Ws = (__half*)(smem + QK_WS);
    __half* Xs = (__half*)(smem + QK_XS);

    const int which = blockIdx.z % 3;
    const int b = blockIdx.z / 3;
    const float* X; const float* W; const float* bias; __half* out; float sc;
    if (which == 0)      { X = x;  W = wq; bias = bq; out = g_q; sc = QSCALE; }
    else if (which == 1) { X = mo; W = wk; bias = bk; out = g_k; sc = 1.0f; }
    else                 { X = mo; W = wv; bias = bv; out = g_v; sc = 1.0f; }
    X   += (size_t)b * CC * NT;
    out += (size_t)b * NT * CC;

    const int n0 = blockIdx.x * 128;
    const int t = threadIdx.x;
    const int warp = t >> 5, lane = t & 31;
    const int dg = warp >> 1, tg = warp & 1;
    const int g = lane >> 2, t4 = lane & 3, l16 = lane & 15;

    for (int idx = t; idx < 16384; idx += 256) {
        const int row = idx >> 6, c4 = idx & 63;
        float4 w4 = *(const float4*)&W[(size_t)row * CC + c4 * 4];
        __half2 h0 = __floats2half2_rn(w4.x, w4.y);
        __half2 h1 = __floats2half2_rn(w4.z, w4.w);
        uint2 u; u.x = *(uint32_t*)&h0; u.y = *(uint32_t*)&h1;
        *(uint2*)&Ws[row * 264 + c4 * 4] = u;
    }
    for (int idx = t; idx < 8192; idx += 256) {
        const int row = idx >> 5, n4 = idx & 31;
        float4 x4 = *(const float4*)&X[(size_t)row * NT + n0 + n4 * 4];
        __half2 h0 = __floats2half2_rn(x4.x, x4.y);
        __half2 h1 = __floats2half2_rn(x4.z, x4.w);
        uint2 u; u.x = *(uint32_t*)&h0; u.y = *(uint32_t*)&h1;
        *(uint2*)&Xs[row * 136 + n4 * 4] = u;
    }
    __syncthreads();

    float oacc[4][8][4];
    #pragma unroll
    for (int qm = 0; qm < 4; qm++)
        #pragma unroll
        for (int nb = 0; nb < 8; nb++)
            #pragma unroll
            for (int e = 0; e < 4; e++) oacc[qm][nb][e] = 0.f;

    #pragma unroll
    for (int ks2 = 0; ks2 < 16; ks2++) {
        uint32_t aW[4][4];
        #pragma unroll
        for (int qm = 0; qm < 4; qm++)
            ldsm_x4(aW[qm], sbase + QK_WS +
                    (uint32_t)(((dg * 64 + qm * 16 + l16) * 264 +
                                ks2 * 16 + (lane >> 4) * 8) * 2));
        #pragma unroll
        for (int pair = 0; pair < 4; pair++) {
            uint32_t bf[4];
            ldsm_x4_t(bf, sbase + QK_XS +
                      (uint32_t)(((ks2 * 16 + l16) * 136 +
                                  tg * 64 + pair * 16 + (lane >> 4) * 8) * 2));
            #pragma unroll
            for (int qm = 0; qm < 4; qm++) {
                mma16816(oacc[qm][pair * 2],     aW[qm], bf);
                mma16816(oacc[qm][pair * 2 + 1], aW[qm], bf + 2);
            }
        }
    }
    __syncthreads();

    {
        __half* sf = (__half*)smem;  // [128][264]
        #pragma unroll
        for (int qm = 0; qm < 4; qm++) {
            const int d0 = dg * 64 + qm * 16 + g, d1 = d0 + 8;
            const float b0 = bias[d0], b1 = bias[d1];
            #pragma unroll
            for (int nb = 0; nb < 8; nb++) {
                const int tok = tg * 64 + nb * 8 + t4 * 2;
                sf[tok * 264 + d0]       = __float2half_rn((oacc[qm][nb][0] + b0) * sc);
                sf[(tok + 1) * 264 + d0] = __float2half_rn((oacc[qm][nb][1] + b0) * sc);
                sf[tok * 264 + d1]       = __float2half_rn((oacc[qm][nb][2] + b1) * sc);
                sf[(tok + 1) * 264 + d1] = __float2half_rn((oacc[qm][nb][3] + b1) * sc);
            }
        }
        __syncthreads();
        const int row = t >> 1, seg = (t & 1) * 128;
        #pragma unroll
        for (int i = 0; i < 16; i++)
            *(uint4*)&out[(size_t)(n0 + row) * CC + seg + i * 8] =
                *(uint4*)&sf[row * 264 + seg + i * 8];
    }
}

// ---------------------------------------------------------------------------
// attn cp.async helpers (512 threads)
// ---------------------------------------------------------------------------
__device__ __forceinline__ void cpa_k(uint32_t sbase, const __half* kb, int k0, int slot, int t) {
    const int row = t >> 3, c8 = t & 7;
    const __half* src = kb + (size_t)(k0 + row) * CC + c8 * 32;
    uint32_t dst = sbase + SM_K + (uint32_t)slot * KSLOT + (uint32_t)(row * QSTR + c8 * 32) * 2;
    #pragma unroll
    for (int i = 0; i < 4; i++) cpa16(dst + i * 16, src + i * 8);
}
__device__ __forceinline__ void cpa_v(uint32_t sbase, const __half* vb, int row0, int slot, int t) {
    const int row = t >> 3, c8 = t & 7;
    const __half* src = vb + (size_t)(row0 + row) * CC + c8 * 32;
    uint32_t dst = sbase + SM_V + (uint32_t)slot * VSLOT + (uint32_t)(row * QSTR + c8 * 32) * 2;
    #pragma unroll
    for (int i = 0; i < 4; i++) cpa16(dst + i * 16, src + i * 8);
}

// ---------------------------------------------------------------------------
// HMMA flash attention: 512 threads = two semi-independent 64-query halves.
// Per half (8 warps): S warp (qg, kg, cs): rows half*64+qg*32, keys kg*32,
// channels cs*128..+128; cs=1 publishes fp16 partials into P slots; cs=0
// combines + exp2 + overwrites P. Named barrier (1+half) between phases.
// PV: warp (half, cg): rows half*64..+64, channels cg*32..+32.
// One full __syncthreads per tile (K/V double-buffer rotation).
// ---------------------------------------------------------------------------
__global__ __launch_bounds__(512, 1) void attn_kernel(float* __restrict__ gout)
{
    extern __shared__ __align__(16) char smem[];
    const uint32_t sbase = smem_u32(smem);
    float* psum = (float*)(smem + SM_PS);   // [2][128]

    const int t = threadIdx.x;
    const int warp = t >> 5, lane = t & 31;
    const int half = warp >> 3;             // 0..1
    const int w8 = warp & 7;
    const int qg = w8 >> 2;                 // 0..1
    const int kg = (w8 >> 1) & 1;           // 0..1
    const int cs = w8 & 1;                  // 0..1 channel half
    const int cg = w8;                      // PV channel group 0..7
    const int g = lane >> 2, t4 = lane & 3, l16 = lane & 15;
    const int qb = half * 64 + qg * 32, cb = kg * 32;
    const int oq = half * 64, cw = cg * 32;

    const int b = blockIdx.y;
    const int i0 = blockIdx.x * TQ;

    const __half* kbase = g_k + (size_t)b * NT * CC;
    const __half* vbase = g_v + (size_t)b * NT * CC;

    cpa_k(sbase, kbase, 0, 0, t);
    cpa_v(sbase, vbase, 0, 0, t);
    CPA_COMMIT();
    {
        const int row = t >> 2, quarter = t & 3;
        const __half* src = g_q + ((size_t)b * NT + i0 + row) * CC + quarter * 64;
        __half* dst = (__half*)(smem + SM_Q) + row * QSTR + quarter * 64;
        #pragma unroll
        for (int i = 0; i < 8; i++)
            *(uint4*)(dst + i * 8) = *(const uint4*)(src + i * 8);
    }
    CPA_WAIT0();
    __syncthreads();

    float oacc[4][4][4];
    #pragma unroll
    for (int qm = 0; qm < 4; qm++)
        #pragma unroll
        for (int nb = 0; nb < 4; nb++)
            #pragma unroll
            for (int e = 0; e < 4; e++) oacc[qm][nb][e] = 0.f;

    float suml[2][2] = {};   // cs==0 warps: [qm][g-half]

    for (int kt = 0; kt < NT / TK; kt++) {
        const int slot = kt & 1;
        const int last = (kt == NT / TK - 1);
        if (!last) {
            cpa_k(sbase, kbase, (kt + 1) * TK, slot ^ 1, t);
            cpa_v(sbase, vbase, (kt + 1) * TK, slot ^ 1, t);
        }
        CPA_COMMIT();

        // ---- S partial: 32q x 32k over this warp's 128 channels ----
        const uint32_t kS = sbase + SM_K + (uint32_t)slot * KSLOT;
        float sacc[2][4][4];
        #pragma unroll
        for (int qm = 0; qm < 2; qm++)
            #pragma unroll
            for (int nb = 0; nb < 4; nb++)
                #pragma unroll
                for (int e = 0; e < 4; e++) sacc[qm][nb][e] = 0.f;

        #pragma unroll
        for (int ks2 = 0; ks2 < 8; ks2++) {
            const int ck = cs * 8 + ks2;
            uint32_t a[2][4];
            #pragma unroll
            for (int qm = 0; qm < 2; qm++)
                ldsm_x4(a[qm], sbase + SM_Q +
                        (uint32_t)(((qb + qm * 16 + l16) * QSTR +
                                    ck * 16 + (lane >> 4) * 8) * 2));
            #pragma unroll
            for (int pair = 0; pair < 2; pair++) {
                uint32_t bf[4];
                ldsm_x4(bf, kS + (uint32_t)(((cb + pair * 16 + (lane >> 4) * 8 + (lane & 7)) * QSTR +
                                             ck * 16 + ((lane >> 3) & 1) * 8) * 2));
                #pragma unroll
                for (int qm = 0; qm < 2; qm++) {
                    mma16816(sacc[qm][pair * 2],     a[qm], bf);
                    mma16816(sacc[qm][pair * 2 + 1], a[qm], bf + 2);
                }
            }
        }

        // cs=1 warps publish fp16 partials into the P buffer slots
        __half* P = (__half*)(smem + SM_P);
        if (cs) {
            #pragma unroll
            for (int qm = 0; qm < 2; qm++) {
                const int ra = qb + qm * 16 + g, rb = ra + 8;
                #pragma unroll
                for (int nb = 0; nb < 4; nb++) {
                    const int col = cb + nb * 8 + t4 * 2;
                    *(__half2*)(P + ra * PSTR + col) =
                        __floats2half2_rn(sacc[qm][nb][0], sacc[qm][nb][1]);
                    *(__half2*)(P + rb * PSTR + col) =
                        __floats2half2_rn(sacc[qm][nb][2], sacc[qm][nb][3]);
                }
            }
        }
        BAR_HALF(half);   // #1: partials ready (this half only)

        // cs=0 warps: combine, exp2, overwrite P in place
        if (!cs) {
            #pragma unroll
            for (int qm = 0; qm < 2; qm++) {
                const int ra = qb + qm * 16 + g, rb = ra + 8;
                #pragma unroll
                for (int nb = 0; nb < 4; nb++) {
                    const int col = cb + nb * 8 + t4 * 2;
                    __half2 xa = *(__half2*)(P + ra * PSTR + col);
                    __half2 xb = *(__half2*)(P + rb * PSTR + col);
                    const float e00 = ex2(sacc[qm][nb][0] + __low2float(xa));
                    const float e01 = ex2(sacc[qm][nb][1] + __high2float(xa));
                    const float e10 = ex2(sacc[qm][nb][2] + __low2float(xb));
                    const float e11 = ex2(sacc[qm][nb][3] + __high2float(xb));
                    suml[qm][0] += e00 + e01; suml[qm][1] += e10 + e11;
                    *(__half2*)(P + ra * PSTR + col) = __floats2half2_rn(e00, e01);
                    *(__half2*)(P + rb * PSTR + col) = __floats2half2_rn(e10, e11);
                }
            }
        }
        BAR_HALF(half);   // #2: P ready (this half only)

        // ---- PV: O[64 q of this half][32 c per warp] += P[64][64] V[64][32] ----
        const uint32_t vS = sbase + SM_V + (uint32_t)slot * VSLOT;
        #pragma unroll
        for (int ks2 = 0; ks2 < 4; ks2++) {
            uint32_t aP[4][4];
            #pragma unroll
            for (int qm = 0; qm < 4; qm++)
                ldsm_x4(aP[qm], sbase + SM_P +
                        (uint32_t)(((oq + qm * 16 + l16) * PSTR +
                                    ks2 * 16 + (lane >> 4) * 8) * 2));
            #pragma unroll
            for (int pair = 0; pair < 2; pair++) {
                uint32_t bf[4];
                ldsm_x4_t(bf, vS + (uint32_t)(((ks2 * 16 + l16) * QSTR +
                                               cw + pair * 16 + (lane >> 4) * 8) * 2));
                #pragma unroll
                for (int qm = 0; qm < 4; qm++) {
                    mma16816(oacc[qm][pair * 2],     aP[qm], bf);
                    mma16816(oacc[qm][pair * 2 + 1], aP[qm], bf + 2);
                }
            }
        }
        CPA_WAIT0();
        __syncthreads();   // rotate K/V slots (only full barrier per tile)
    }

    // final row-sum reduction (cs==0 warps, partials indexed by kg)
    #pragma unroll
    for (int qm = 0; qm < 2; qm++)
        #pragma unroll
        for (int h = 0; h < 2; h++) {
            suml[qm][h] += __shfl_xor_sync(0xffffffffu, suml[qm][h], 1);
            suml[qm][h] += __shfl_xor_sync(0xffffffffu, suml[qm][h], 2);
        }
    if (!cs && t4 == 0) {
        #pragma unroll
        for (int qm = 0; qm < 2; qm++) {
            psum[kg * 128 + qb + qm * 16 + g]     = suml[qm][0];
            psum[kg * 128 + qb + qm * 16 + g + 8] = suml[qm][1];
        }
    }
    __syncthreads();

    // normalize + stage O^T [c][q] (fp32 [256][132]), coalesced store
    {
        float* sf = (float*)smem;
        float inv0[4], inv1[4];
        #pragma unroll
        for (int qm = 0; qm < 4; qm++) {
            const int ra = oq + qm * 16 + g, rb = ra + 8;
            inv0[qm] = 1.f / (psum[ra] + psum[128 + ra]);
            inv1[qm] = 1.f / (psum[rb] + psum[128 + rb]);
        }
        __syncthreads();
        #pragma unroll
        for (int qm = 0; qm < 4; qm++) {
            const int ra = oq + qm * 16 + g, rb = ra + 8;
            #pragma unroll
            for (int nb = 0; nb < 4; nb++) {
                const int col = cw + nb * 8 + t4 * 2;
                sf[col * 132 + ra]       = oacc[qm][nb][0] * inv0[qm];
                sf[(col + 1) * 132 + ra] = oacc[qm][nb][1] * inv0[qm];
                sf[col * 132 + rb]       = oacc[qm][nb][2] * inv1[qm];
                sf[(col + 1) * 132 + rb] = oacc[qm][nb][3] * inv1[qm];
            }
        }
        __syncthreads();
        float* obase = gout + (size_t)b * CC * NT + i0;
        #pragma unroll
        for (int pass = 0; pass < 2; pass++) {
            const int c = (t >> 2) + pass * 128;
            const int q0 = (t & 3) * 32;
            #pragma unroll
            for (int i = 0; i < 8; i++)
                *(float4*)&obase[(size_t)c * NT + q0 + i * 4] =
                    *(float4*)&sf[c * 132 + q0 + i * 4];
        }
    }
}

extern "C" void kernel_launch(void* const* d_in, const int* in_sizes, int n_in,
                              void* d_out, int out_size)
{
    const float* x  = (const float*)d_in[0];
    const float* mo = (const float*)d_in[1];
    const float* wq = (const float*)d_in[2];
    const float* bq = (const float*)d_in[3];
    const float* wk = (const float*)d_in[4];
    const float* bk = (const float*)d_in[5];
    const float* wv = (const float*)d_in[6];
    const float* bv = (const float*)d_in[7];
    float* out = (float*)d_out;

    cudaFuncSetAttribute(qkv_kernel, cudaFuncAttributeMaxDynamicSharedMemorySize,
                         (int)QK_SMEM);
    dim3 g1(NT / 128, 1, BB * 3);
    qkv_kernel<<<g1, 256, QK_SMEM>>>(x, mo, wq, bq, wk, bk, wv, bv);

    cudaFuncSetAttribute(attn_kernel, cudaFuncAttributeMaxDynamicSharedMemorySize,
                         (int)SMEM_BYTES);
    dim3 g2(NT / TQ, BB);
    attn_kernel<<<g2, 512, SMEM_BYTES>>>(out);
}

// round 14
// speedup vs baseline: 1.3057x; 1.0175x over previous
#include <cuda_runtime.h>
#include <cuda_fp16.h>
#include <stdint.h>
#include <math.h>

#define CC 256
#define NT 4096
#define BB 8
#define TQ 128         // queries per CTA (four independent 32-row quarters)
#define TK 64          // keys per tile
#define QSTR 264       // half stride of Q/K/V SMEM rows (528B)
#define PSTR 72        // half stride of P / partial-exchange buffer (144B)

// Q pre-scale folds softmax scale (1/16) and log2(e) so P = exp2(S_mma)
#define QSCALE 0.0901684403f

// fp16 scratch, all [b][n][c]
__device__ __half g_q[(size_t)BB * NT * CC];
__device__ __half g_k[(size_t)BB * NT * CC];
__device__ __half g_v[(size_t)BB * NT * CC];

// attn SMEM byte offsets
#define SM_Q   0u          // 128 x 264 fp16 = 67584
#define SM_K   67584u      // 2 slots x 64 x 264 fp16 = 67584
#define KSLOT  33792u
#define SM_V   135168u     // 2 slots x 64 x 264 fp16 = 67584
#define VSLOT  33792u
#define SM_P   202752u     // fp16 [128][72] = 18432 (partials then P, in place)
#define SM_PS  221184u     // float[2][128] = 1024
#define SMEM_BYTES 222208u

// qkv SMEM: Ws [256][264] fp16 = 135168, Xs [256][136] fp16 = 69632
// epilogue staging sf [128][264] fp16 = 67584 lives in the Xs region
#define QK_WS   0u
#define QK_XS   135168u
#define QK_SMEM 204800u

__device__ __forceinline__ uint32_t smem_u32(const void* p) {
    uint32_t a;
    asm("{ .reg .u64 t; cvta.to.shared.u64 t, %1; cvt.u32.u64 %0, t; }" : "=r"(a) : "l"(p));
    return a;
}
__device__ __forceinline__ float ex2(float x) {
    float y; asm("ex2.approx.ftz.f32 %0, %1;" : "=f"(y) : "f"(x)); return y;
}
__device__ __forceinline__ void ldsm_x4(uint32_t* r, uint32_t a) {
    asm volatile("ldmatrix.sync.aligned.m8n8.x4.shared.b16 {%0,%1,%2,%3}, [%4];"
        : "=r"(r[0]), "=r"(r[1]), "=r"(r[2]), "=r"(r[3]) : "r"(a));
}
__device__ __forceinline__ void ldsm_x4_t(uint32_t* r, uint32_t a) {
    asm volatile("ldmatrix.sync.aligned.m8n8.x4.trans.shared.b16 {%0,%1,%2,%3}, [%4];"
        : "=r"(r[0]), "=r"(r[1]), "=r"(r[2]), "=r"(r[3]) : "r"(a));
}
__device__ __forceinline__ void mma16816(float* c, const uint32_t* a, const uint32_t* b) {
    asm volatile("mma.sync.aligned.m16n8k16.row.col.f32.f16.f16.f32 "
        "{%0,%1,%2,%3}, {%4,%5,%6,%7}, {%8,%9}, {%0,%1,%2,%3};"
        : "+f"(c[0]), "+f"(c[1]), "+f"(c[2]), "+f"(c[3])
        : "r"(a[0]), "r"(a[1]), "r"(a[2]), "r"(a[3]), "r"(b[0]), "r"(b[1]));
}
__device__ __forceinline__ void cpa16(uint32_t s, const void* g) {
    asm volatile("cp.async.cg.shared.global [%0], [%1], 16;" :: "r"(s), "l"(g));
}
#define CPA_COMMIT() asm volatile("cp.async.commit_group;" ::: "memory")
#define CPA_WAIT0()  asm volatile("cp.async.wait_group 0;" ::: "memory")
#define BAR_Q(q)     asm volatile("bar.sync %0, 128;" :: "r"(1 + (q)) : "memory")

// ---------------------------------------------------------------------------
// QKV projection via HMMA: 256 tokens per CTA (W loaded once, 2 X tiles).
// ---------------------------------------------------------------------------
__global__ __launch_bounds__(256, 1) void qkv_kernel(
    const float* __restrict__ x, const float* __restrict__ mo,
    const float* __restrict__ wq, const float* __restrict__ bq,
    const float* __restrict__ wk, const float* __restrict__ bk,
    const float* __restrict__ wv, const float* __restrict__ bv)
{
    extern __shared__ __align__(16) char smem[];
    const uint32_t sbase = smem_u32(smem);
    __half* Ws = (__half*)(smem + QK_WS);
    __half* Xs = (__half*)(smem + QK_XS);

    const int which = blockIdx.z % 3;
    const int b = blockIdx.z / 3;
    const float* X; const float* W; const float* bias; __half* out; float sc;
    if (which == 0)      { X = x;  W = wq; bias = bq; out = g_q; sc = QSCALE; }
    else if (which == 1) { X = mo; W = wk; bias = bk; out = g_k; sc = 1.0f; }
    else                 { X = mo; W = wv; bias = bv; out = g_v; sc = 1.0f; }
    X   += (size_t)b * CC * NT;
    out += (size_t)b * NT * CC;

    const int t = threadIdx.x;
    const int warp = t >> 5, lane = t & 31;
    const int dg = warp >> 1, tg = warp & 1;
    const int g = lane >> 2, t4 = lane & 3, l16 = lane & 15;

    // load W once [256][256] fp32 -> fp16 stride 264
    for (int idx = t; idx < 16384; idx += 256) {
        const int row = idx >> 6, c4 = idx & 63;
        float4 w4 = *(const float4*)&W[(size_t)row * CC + c4 * 4];
        __half2 h0 = __floats2half2_rn(w4.x, w4.y);
        __half2 h1 = __floats2half2_rn(w4.z, w4.w);
        uint2 u; u.x = *(uint32_t*)&h0; u.y = *(uint32_t*)&h1;
        *(uint2*)&Ws[row * 264 + c4 * 4] = u;
    }

    for (int ntile = 0; ntile < 2; ntile++) {
        const int n0 = blockIdx.x * 256 + ntile * 128;
        __syncthreads();   // Ws ready / previous epilogue reads done

        // X tile [256 c][128 n] fp32 -> fp16 stride 136
        for (int idx = t; idx < 8192; idx += 256) {
            const int row = idx >> 5, n4 = idx & 31;
            float4 x4 = *(const float4*)&X[(size_t)row * NT + n0 + n4 * 4];
            __half2 h0 = __floats2half2_rn(x4.x, x4.y);
            __half2 h1 = __floats2half2_rn(x4.z, x4.w);
            uint2 u; u.x = *(uint32_t*)&h0; u.y = *(uint32_t*)&h1;
            *(uint2*)&Xs[row * 136 + n4 * 4] = u;
        }
        __syncthreads();

        float oacc[4][8][4];
        #pragma unroll
        for (int qm = 0; qm < 4; qm++)
            #pragma unroll
            for (int nb = 0; nb < 8; nb++)
                #pragma unroll
                for (int e = 0; e < 4; e++) oacc[qm][nb][e] = 0.f;

        #pragma unroll
        for (int ks2 = 0; ks2 < 16; ks2++) {
            uint32_t aW[4][4];
            #pragma unroll
            for (int qm = 0; qm < 4; qm++)
                ldsm_x4(aW[qm], sbase + QK_WS +
                        (uint32_t)(((dg * 64 + qm * 16 + l16) * 264 +
                                    ks2 * 16 + (lane >> 4) * 8) * 2));
            #pragma unroll
            for (int pair = 0; pair < 4; pair++) {
                uint32_t bf[4];
                ldsm_x4_t(bf, sbase + QK_XS +
                          (uint32_t)(((ks2 * 16 + l16) * 136 +
                                      tg * 64 + pair * 16 + (lane >> 4) * 8) * 2));
                #pragma unroll
                for (int qm = 0; qm < 4; qm++) {
                    mma16816(oacc[qm][pair * 2],     aW[qm], bf);
                    mma16816(oacc[qm][pair * 2 + 1], aW[qm], bf + 2);
                }
            }
        }
        __syncthreads();   // Xs reads done before sf overlay

        // epilogue: bias+scale, fp16, stage sf[tok][264] in Xs region, store
        {
            __half* sf = (__half*)(smem + QK_XS);  // [128][264] -- fits 69632
            #pragma unroll
            for (int qm = 0; qm < 4; qm++) {
                const int d0 = dg * 64 + qm * 16 + g, d1 = d0 + 8;
                const float b0 = bias[d0], b1 = bias[d1];
                #pragma unroll
                for (int nb = 0; nb < 8; nb++) {
                    const int tok = tg * 64 + nb * 8 + t4 * 2;
                    sf[tok * 264 + d0]       = __float2half_rn((oacc[qm][nb][0] + b0) * sc);
                    sf[(tok + 1) * 264 + d0] = __float2half_rn((oacc[qm][nb][1] + b0) * sc);
                    sf[tok * 264 + d1]       = __float2half_rn((oacc[qm][nb][2] + b1) * sc);
                    sf[(tok + 1) * 264 + d1] = __float2half_rn((oacc[qm][nb][3] + b1) * sc);
                }
            }
            __syncthreads();
            const int row = t >> 1, seg = (t & 1) * 128;
            #pragma unroll
            for (int i = 0; i < 16; i++)
                *(uint4*)&out[(size_t)(n0 + row) * CC + seg + i * 8] =
                    *(uint4*)&sf[row * 264 + seg + i * 8];
        }
    }
}

// ---------------------------------------------------------------------------
// attn cp.async helpers (512 threads)
// ---------------------------------------------------------------------------
__device__ __forceinline__ void cpa_k(uint32_t sbase, const __half* kb, int k0, int slot, int t) {
    const int row = t >> 3, c8 = t & 7;
    const __half* src = kb + (size_t)(k0 + row) * CC + c8 * 32;
    uint32_t dst = sbase + SM_K + (uint32_t)slot * KSLOT + (uint32_t)(row * QSTR + c8 * 32) * 2;
    #pragma unroll
    for (int i = 0; i < 4; i++) cpa16(dst + i * 16, src + i * 8);
}
__device__ __forceinline__ void cpa_v(uint32_t sbase, const __half* vb, int row0, int slot, int t) {
    const int row = t >> 3, c8 = t & 7;
    const __half* src = vb + (size_t)(row0 + row) * CC + c8 * 32;
    uint32_t dst = sbase + SM_V + (uint32_t)slot * VSLOT + (uint32_t)(row * QSTR + c8 * 32) * 2;
    #pragma unroll
    for (int i = 0; i < 4; i++) cpa16(dst + i * 16, src + i * 8);
}

// ---------------------------------------------------------------------------
// HMMA flash attention: 512 threads = four independent 32-query quarters.
// Per quarter (4 warps): S warp (kg, cs): rows quarter*32..+32, keys kg*32,
// channels cs*128..+128; cs=1 publishes fp16 partials into P slots; cs=0
// combines + exp2 + overwrites P. Named barrier (1+quarter, 128 threads).
// PV: warp covers rows quarter*32..+32, channels (warp&3)*64..+64.
// One full __syncthreads per tile (K/V double-buffer rotation).
// ---------------------------------------------------------------------------
__global__ __launch_bounds__(512, 1) void attn_kernel(float* __restrict__ gout)
{
    extern __shared__ __align__(16) char smem[];
    const uint32_t sbase = smem_u32(smem);
    float* psum = (float*)(smem + SM_PS);   // [2][128]

    const int t = threadIdx.x;
    const int warp = t >> 5, lane = t & 31;
    const int quarter = warp >> 2;          // 0..3
    const int wq = warp & 3;
    const int kg = wq >> 1;                 // 0..1
    const int cs = wq & 1;                  // 0..1 channel half
    const int g = lane >> 2, t4 = lane & 3, l16 = lane & 15;
    const int qb = quarter * 32, cb = kg * 32;
    const int cw = wq * 64;                 // PV channel base

    const int b = blockIdx.y;
    const int i0 = blockIdx.x * TQ;

    const __half* kbase = g_k + (size_t)b * NT * CC;
    const __half* vbase = g_v + (size_t)b * NT * CC;

    cpa_k(sbase, kbase, 0, 0, t);
    cpa_v(sbase, vbase, 0, 0, t);
    CPA_COMMIT();
    {
        const int row = t >> 2, quarter4 = t & 3;
        const __half* src = g_q + ((size_t)b * NT + i0 + row) * CC + quarter4 * 64;
        __half* dst = (__half*)(smem + SM_Q) + row * QSTR + quarter4 * 64;
        #pragma unroll
        for (int i = 0; i < 8; i++)
            *(uint4*)(dst + i * 8) = *(const uint4*)(src + i * 8);
    }
    CPA_WAIT0();
    __syncthreads();

    float oacc[2][8][4];   // [qm][nb]: rows qb+qm*16+{g,g+8}, cols cw+nb*8+2t4
    #pragma unroll
    for (int qm = 0; qm < 2; qm++)
        #pragma unroll
        for (int nb = 0; nb < 8; nb++)
            #pragma unroll
            for (int e = 0; e < 4; e++) oacc[qm][nb][e] = 0.f;

    float suml[2][2] = {};   // cs==0 warps: [qm][g-half]

    for (int kt = 0; kt < NT / TK; kt++) {
        const int slot = kt & 1;
        const int last = (kt == NT / TK - 1);
        if (!last) {
            cpa_k(sbase, kbase, (kt + 1) * TK, slot ^ 1, t);
            cpa_v(sbase, vbase, (kt + 1) * TK, slot ^ 1, t);
        }
        CPA_COMMIT();

        // ---- S partial: 32q x 32k over this warp's 128 channels ----
        const uint32_t kS = sbase + SM_K + (uint32_t)slot * KSLOT;
        float sacc[2][4][4];
        #pragma unroll
        for (int qm = 0; qm < 2; qm++)
            #pragma unroll
            for (int nb = 0; nb < 4; nb++)
                #pragma unroll
                for (int e = 0; e < 4; e++) sacc[qm][nb][e] = 0.f;

        #pragma unroll
        for (int ks2 = 0; ks2 < 8; ks2++) {
            const int ck = cs * 8 + ks2;
            uint32_t a[2][4];
            #pragma unroll
            for (int qm = 0; qm < 2; qm++)
                ldsm_x4(a[qm], sbase + SM_Q +
                        (uint32_t)(((qb + qm * 16 + l16) * QSTR +
                                    ck * 16 + (lane >> 4) * 8) * 2));
            #pragma unroll
            for (int pair = 0; pair < 2; pair++) {
                uint32_t bf[4];
                ldsm_x4(bf, kS + (uint32_t)(((cb + pair * 16 + (lane >> 4) * 8 + (lane & 7)) * QSTR +
                                             ck * 16 + ((lane >> 3) & 1) * 8) * 2));
                #pragma unroll
                for (int qm = 0; qm < 2; qm++) {
                    mma16816(sacc[qm][pair * 2],     a[qm], bf);
                    mma16816(sacc[qm][pair * 2 + 1], a[qm], bf + 2);
                }
            }
        }

        // cs=1 warps publish fp16 partials into the P buffer slots
        __half* P = (__half*)(smem + SM_P);
        if (cs) {
            #pragma unroll
            for (int qm = 0; qm < 2; qm++) {
                const int ra = qb + qm * 16 + g, rb = ra + 8;
                #pragma unroll
                for (int nb = 0; nb < 4; nb++) {
                    const int col = cb + nb * 8 + t4 * 2;
                    *(__half2*)(P + ra * PSTR + col) =
                        __floats2half2_rn(sacc[qm][nb][0], sacc[qm][nb][1]);
                    *(__half2*)(P + rb * PSTR + col) =
                        __floats2half2_rn(sacc[qm][nb][2], sacc[qm][nb][3]);
                }
            }
        }
        BAR_Q(quarter);   // #1: partials ready (this quarter only)

        // cs=0 warps: combine, exp2, overwrite P in place
        if (!cs) {
            #pragma unroll
            for (int qm = 0; qm < 2; qm++) {
                const int ra = qb + qm * 16 + g, rb = ra + 8;
                #pragma unroll
                for (int nb = 0; nb < 4; nb++) {
                    const int col = cb + nb * 8 + t4 * 2;
                    __half2 xa = *(__half2*)(P + ra * PSTR + col);
                    __half2 xb = *(__half2*)(P + rb * PSTR + col);
                    const float e00 = ex2(sacc[qm][nb][0] + __low2float(xa));
                    const float e01 = ex2(sacc[qm][nb][1] + __high2float(xa));
                    const float e10 = ex2(sacc[qm][nb][2] + __low2float(xb));
                    const float e11 = ex2(sacc[qm][nb][3] + __high2float(xb));
                    suml[qm][0] += e00 + e01; suml[qm][1] += e10 + e11;
                    *(__half2*)(P + ra * PSTR + col) = __floats2half2_rn(e00, e01);
                    *(__half2*)(P + rb * PSTR + col) = __floats2half2_rn(e10, e11);
                }
            }
        }
        BAR_Q(quarter);   // #2: P ready (this quarter only)

        // ---- PV: O[32 q of this quarter][64 c per warp] += P[32][64] V[64][64] ----
        const uint32_t vS = sbase + SM_V + (uint32_t)slot * VSLOT;
        #pragma unroll
        for (int ks2 = 0; ks2 < 4; ks2++) {
            uint32_t aP[2][4];
            #pragma unroll
            for (int qm = 0; qm < 2; qm++)
                ldsm_x4(aP[qm], sbase + SM_P +
                        (uint32_t)(((qb + qm * 16 + l16) * PSTR +
                                    ks2 * 16 + (lane >> 4) * 8) * 2));
            #pragma unroll
            for (int pair = 0; pair < 4; pair++) {
                uint32_t bf[4];
                ldsm_x4_t(bf, vS + (uint32_t)(((ks2 * 16 + l16) * QSTR +
                                               cw + pair * 16 + (lane >> 4) * 8) * 2));
                #pragma unroll
                for (int qm = 0; qm < 2; qm++) {
                    mma16816(oacc[qm][pair * 2],     aP[qm], bf);
                    mma16816(oacc[qm][pair * 2 + 1], aP[qm], bf + 2);
                }
            }
        }
        CPA_WAIT0();
        __syncthreads();   // rotate K/V slots (only full barrier per tile)
    }

    // final row-sum reduction (cs==0 warps, partials indexed by kg)
    #pragma unroll
    for (int qm = 0; qm < 2; qm++)
        #pragma unroll
        for (int h = 0; h < 2; h++) {
            suml[qm][h] += __shfl_xor_sync(0xffffffffu, suml[qm][h], 1);
            suml[qm][h] += __shfl_xor_sync(0xffffffffu, suml[qm][h], 2);
        }
    if (!cs && t4 == 0) {
        #pragma unroll
        for (int qm = 0; qm < 2; qm++) {
            psum[kg * 128 + qb + qm * 16 + g]     = suml[qm][0];
            psum[kg * 128 + qb + qm * 16 + g + 8] = suml[qm][1];
        }
    }
    __syncthreads();

    // normalize + stage O^T [c][q] (fp32 [256][132]), coalesced store
    {
        float* sf = (float*)smem;
        float inv0[2], inv1[2];
        #pragma unroll
        for (int qm = 0; qm < 2; qm++) {
            const int ra = qb + qm * 16 + g, rb = ra + 8;
            inv0[qm] = 1.f / (psum[ra] + psum[128 + ra]);
            inv1[qm] = 1.f / (psum[rb] + psum[128 + rb]);
        }
        __syncthreads();
        #pragma unroll
        for (int qm = 0; qm < 2; qm++) {
            const int ra = qb + qm * 16 + g, rb = ra + 8;
            #pragma unroll
            for (int nb = 0; nb < 8; nb++) {
                const int col = cw + nb * 8 + t4 * 2;
                sf[col * 132 + ra]       = oacc[qm][nb][0] * inv0[qm];
                sf[(col + 1) * 132 + ra] = oacc[qm][nb][1] * inv0[qm];
                sf[col * 132 + rb]       = oacc[qm][nb][2] * inv1[qm];
                sf[(col + 1) * 132 + rb] = oacc[qm][nb][3] * inv1[qm];
            }
        }
        __syncthreads();
        float* obase = gout + (size_t)b * CC * NT + i0;
        #pragma unroll
        for (int pass = 0; pass < 2; pass++) {
            const int c = (t >> 2) + pass * 128;
            const int q0 = (t & 3) * 32;
            #pragma unroll
            for (int i = 0; i < 8; i++)
                *(float4*)&obase[(size_t)c * NT + q0 + i * 4] =
                    *(float4*)&sf[c * 132 + q0 + i * 4];
        }
    }
}

extern "C" void kernel_launch(void* const* d_in, const int* in_sizes, int n_in,
                              void* d_out, int out_size)
{
    const float* x  = (const float*)d_in[0];
    const float* mo = (const float*)d_in[1];
    const float* wq = (const float*)d_in[2];
    const float* bq = (const float*)d_in[3];
    const float* wk = (const float*)d_in[4];
    const float* bk = (const float*)d_in[5];
    const float* wv = (const float*)d_in[6];
    const float* bv = (const float*)d_in[7];
    float* out = (float*)d_out;

    cudaFuncSetAttribute(qkv_kernel, cudaFuncAttributeMaxDynamicSharedMemorySize,
                         (int)QK_SMEM);
    dim3 g1(NT / 256, 1, BB * 3);
    qkv_kernel<<<g1, 256, QK_SMEM>>>(x, mo, wq, bq, wk, bk, wv, bv);

    cudaFuncSetAttribute(attn_kernel, cudaFuncAttributeMaxDynamicSharedMemorySize,
                         (int)SMEM_BYTES);
    dim3 g2(NT / TQ, BB);
    attn_kernel<<<g2, 512, SMEM_BYTES>>>(out);
}

// round 15
// speedup vs baseline: 1.3146x; 1.0068x over previous
#include <cuda_runtime.h>
#include <cuda_fp16.h>
#include <stdint.h>
#include <math.h>

#define CC 256
#define NT 4096
#define BB 8
#define TQ 128         // queries per CTA (four independent 32-row quarters)
#define TK 64          // keys per tile
#define QSTR 264       // half stride of Q/K/V SMEM rows (528B)
#define PSTR 72        // half stride of P / partial-exchange buffer (144B)

// Q pre-scale folds softmax scale (1/16) and log2(e) so P = exp2(S_mma)
#define QSCALE 0.0901684403f

// fp16 scratch, all [b][n][c]
__device__ __half g_q[(size_t)BB * NT * CC];
__device__ __half g_k[(size_t)BB * NT * CC];
__device__ __half g_v[(size_t)BB * NT * CC];

// attn SMEM byte offsets
#define SM_Q   0u          // 128 x 264 fp16 = 67584
#define SM_K   67584u      // 2 slots x 64 x 264 fp16 = 67584
#define KSLOT  33792u
#define SM_V   135168u     // 2 slots x 64 x 264 fp16 = 67584
#define VSLOT  33792u
#define SM_P   202752u     // fp16 [128][72] = 18432 (partials then P, in place)
#define SM_PS  221184u     // float[2][128] = 1024
#define SMEM_BYTES 222208u

// qkv SMEM: Ws [256][264] fp16 = 135168, Xs [256][136] fp16 = 69632
#define QK_WS   0u
#define QK_XS   135168u
#define QK_SMEM 204800u

__device__ __forceinline__ uint32_t smem_u32(const void* p) {
    uint32_t a;
    asm("{ .reg .u64 t; cvta.to.shared.u64 t, %1; cvt.u32.u64 %0, t; }" : "=r"(a) : "l"(p));
    return a;
}
__device__ __forceinline__ __half2 h2ex2(__half2 x) {
    __half2 y;
    asm("ex2.approx.f16x2 %0, %1;" : "=r"(*(uint32_t*)&y) : "r"(*(uint32_t*)&x));
    return y;
}
__device__ __forceinline__ void ldsm_x4(uint32_t* r, uint32_t a) {
    asm volatile("ldmatrix.sync.aligned.m8n8.x4.shared.b16 {%0,%1,%2,%3}, [%4];"
        : "=r"(r[0]), "=r"(r[1]), "=r"(r[2]), "=r"(r[3]) : "r"(a));
}
__device__ __forceinline__ void ldsm_x4_t(uint32_t* r, uint32_t a) {
    asm volatile("ldmatrix.sync.aligned.m8n8.x4.trans.shared.b16 {%0,%1,%2,%3}, [%4];"
        : "=r"(r[0]), "=r"(r[1]), "=r"(r[2]), "=r"(r[3]) : "r"(a));
}
__device__ __forceinline__ void mma16816(float* c, const uint32_t* a, const uint32_t* b) {
    asm volatile("mma.sync.aligned.m16n8k16.row.col.f32.f16.f16.f32 "
        "{%0,%1,%2,%3}, {%4,%5,%6,%7}, {%8,%9}, {%0,%1,%2,%3};"
        : "+f"(c[0]), "+f"(c[1]), "+f"(c[2]), "+f"(c[3])
        : "r"(a[0]), "r"(a[1]), "r"(a[2]), "r"(a[3]), "r"(b[0]), "r"(b[1]));
}
__device__ __forceinline__ void cpa16(uint32_t s, const void* g) {
    asm volatile("cp.async.cg.shared.global [%0], [%1], 16;" :: "r"(s), "l"(g));
}
#define CPA_COMMIT() asm volatile("cp.async.commit_group;" ::: "memory")
#define CPA_WAIT0()  asm volatile("cp.async.wait_group 0;" ::: "memory")
#define BAR_Q(q)     asm volatile("bar.sync %0, 128;" :: "r"(1 + (q)) : "memory")

// ---------------------------------------------------------------------------
// QKV projection via HMMA: 256 tokens per CTA (W loaded once, 2 X tiles).
// ---------------------------------------------------------------------------
__global__ __launch_bounds__(256, 1) void qkv_kernel(
    const float* __restrict__ x, const float* __restrict__ mo,
    const float* __restrict__ wq, const float* __restrict__ bq,
    const float* __restrict__ wk, const float* __restrict__ bk,
    const float* __restrict__ wv, const float* __restrict__ bv)
{
    extern __shared__ __align__(16) char smem[];
    const uint32_t sbase = smem_u32(smem);
    __half* Ws = (__half*)(smem + QK_WS);
    __half* Xs = (__half*)(smem + QK_XS);

    const int which = blockIdx.z % 3;
    const int b = blockIdx.z / 3;
    const float* X; const float* W; const float* bias; __half* out; float sc;
    if (which == 0)      { X = x;  W = wq; bias = bq; out = g_q; sc = QSCALE; }
    else if (which == 1) { X = mo; W = wk; bias = bk; out = g_k; sc = 1.0f; }
    else                 { X = mo; W = wv; bias = bv; out = g_v; sc = 1.0f; }
    X   += (size_t)b * CC * NT;
    out += (size_t)b * NT * CC;

    const int t = threadIdx.x;
    const int warp = t >> 5, lane = t & 31;
    const int dg = warp >> 1, tg = warp & 1;
    const int g = lane >> 2, t4 = lane & 3, l16 = lane & 15;

    for (int idx = t; idx < 16384; idx += 256) {
        const int row = idx >> 6, c4 = idx & 63;
        float4 w4 = *(const float4*)&W[(size_t)row * CC + c4 * 4];
        __half2 h0 = __floats2half2_rn(w4.x, w4.y);
        __half2 h1 = __floats2half2_rn(w4.z, w4.w);
        uint2 u; u.x = *(uint32_t*)&h0; u.y = *(uint32_t*)&h1;
        *(uint2*)&Ws[row * 264 + c4 * 4] = u;
    }

    for (int ntile = 0; ntile < 2; ntile++) {
        const int n0 = blockIdx.x * 256 + ntile * 128;
        __syncthreads();

        for (int idx = t; idx < 8192; idx += 256) {
            const int row = idx >> 5, n4 = idx & 31;
            float4 x4 = *(const float4*)&X[(size_t)row * NT + n0 + n4 * 4];
            __half2 h0 = __floats2half2_rn(x4.x, x4.y);
            __half2 h1 = __floats2half2_rn(x4.z, x4.w);
            uint2 u; u.x = *(uint32_t*)&h0; u.y = *(uint32_t*)&h1;
            *(uint2*)&Xs[row * 136 + n4 * 4] = u;
        }
        __syncthreads();

        float oacc[4][8][4];
        #pragma unroll
        for (int qm = 0; qm < 4; qm++)
            #pragma unroll
            for (int nb = 0; nb < 8; nb++)
                #pragma unroll
                for (int e = 0; e < 4; e++) oacc[qm][nb][e] = 0.f;

        #pragma unroll
        for (int ks2 = 0; ks2 < 16; ks2++) {
            uint32_t aW[4][4];
            #pragma unroll
            for (int qm = 0; qm < 4; qm++)
                ldsm_x4(aW[qm], sbase + QK_WS +
                        (uint32_t)(((dg * 64 + qm * 16 + l16) * 264 +
                                    ks2 * 16 + (lane >> 4) * 8) * 2));
            #pragma unroll
            for (int pair = 0; pair < 4; pair++) {
                uint32_t bf[4];
                ldsm_x4_t(bf, sbase + QK_XS +
                          (uint32_t)(((ks2 * 16 + l16) * 136 +
                                      tg * 64 + pair * 16 + (lane >> 4) * 8) * 2));
                #pragma unroll
                for (int qm = 0; qm < 4; qm++) {
                    mma16816(oacc[qm][pair * 2],     aW[qm], bf);
                    mma16816(oacc[qm][pair * 2 + 1], aW[qm], bf + 2);
                }
            }
        }
        __syncthreads();

        {
            __half* sf = (__half*)(smem + QK_XS);  // [128][264]
            #pragma unroll
            for (int qm = 0; qm < 4; qm++) {
                const int d0 = dg * 64 + qm * 16 + g, d1 = d0 + 8;
                const float b0 = bias[d0], b1 = bias[d1];
                #pragma unroll
                for (int nb = 0; nb < 8; nb++) {
                    const int tok = tg * 64 + nb * 8 + t4 * 2;
                    sf[tok * 264 + d0]       = __float2half_rn((oacc[qm][nb][0] + b0) * sc);
                    sf[(tok + 1) * 264 + d0] = __float2half_rn((oacc[qm][nb][1] + b0) * sc);
                    sf[tok * 264 + d1]       = __float2half_rn((oacc[qm][nb][2] + b1) * sc);
                    sf[(tok + 1) * 264 + d1] = __float2half_rn((oacc[qm][nb][3] + b1) * sc);
                }
            }
            __syncthreads();
            const int row = t >> 1, seg = (t & 1) * 128;
            #pragma unroll
            for (int i = 0; i < 16; i++)
                *(uint4*)&out[(size_t)(n0 + row) * CC + seg + i * 8] =
                    *(uint4*)&sf[row * 264 + seg + i * 8];
        }
    }
}

// ---------------------------------------------------------------------------
// attn cp.async helpers (512 threads)
// ---------------------------------------------------------------------------
__device__ __forceinline__ void cpa_k(uint32_t sbase, const __half* kb, int k0, int slot, int t) {
    const int row = t >> 3, c8 = t & 7;
    const __half* src = kb + (size_t)(k0 + row) * CC + c8 * 32;
    uint32_t dst = sbase + SM_K + (uint32_t)slot * KSLOT + (uint32_t)(row * QSTR + c8 * 32) * 2;
    #pragma unroll
    for (int i = 0; i < 4; i++) cpa16(dst + i * 16, src + i * 8);
}
__device__ __forceinline__ void cpa_v(uint32_t sbase, const __half* vb, int row0, int slot, int t) {
    const int row = t >> 3, c8 = t & 7;
    const __half* src = vb + (size_t)(row0 + row) * CC + c8 * 32;
    uint32_t dst = sbase + SM_V + (uint32_t)slot * VSLOT + (uint32_t)(row * QSTR + c8 * 32) * 2;
    #pragma unroll
    for (int i = 0; i < 4; i++) cpa16(dst + i * 16, src + i * 8);
}

// ---------------------------------------------------------------------------
// HMMA flash attention: 512 threads = four independent 32-query quarters.
// R14 structure; softmax combine+exp now in fp16x2 (ex2.approx.f16x2).
// ---------------------------------------------------------------------------
__global__ __launch_bounds__(512, 1) void attn_kernel(float* __restrict__ gout)
{
    extern __shared__ __align__(16) char smem[];
    const uint32_t sbase = smem_u32(smem);
    float* psum = (float*)(smem + SM_PS);   // [2][128]

    const int t = threadIdx.x;
    const int warp = t >> 5, lane = t & 31;
    const int quarter = warp >> 2;          // 0..3
    const int wq = warp & 3;
    const int kg = wq >> 1;                 // 0..1
    const int cs = wq & 1;                  // 0..1 channel half
    const int g = lane >> 2, t4 = lane & 3, l16 = lane & 15;
    const int qb = quarter * 32, cb = kg * 32;
    const int cw = wq * 64;                 // PV channel base

    const int b = blockIdx.y;
    const int i0 = blockIdx.x * TQ;

    const __half* kbase = g_k + (size_t)b * NT * CC;
    const __half* vbase = g_v + (size_t)b * NT * CC;

    cpa_k(sbase, kbase, 0, 0, t);
    cpa_v(sbase, vbase, 0, 0, t);
    CPA_COMMIT();
    {
        const int row = t >> 2, quarter4 = t & 3;
        const __half* src = g_q + ((size_t)b * NT + i0 + row) * CC + quarter4 * 64;
        __half* dst = (__half*)(smem + SM_Q) + row * QSTR + quarter4 * 64;
        #pragma unroll
        for (int i = 0; i < 8; i++)
            *(uint4*)(dst + i * 8) = *(const uint4*)(src + i * 8);
    }
    CPA_WAIT0();
    __syncthreads();

    float oacc[2][8][4];   // [qm][nb]: rows qb+qm*16+{g,g+8}, cols cw+nb*8+2t4
    #pragma unroll
    for (int qm = 0; qm < 2; qm++)
        #pragma unroll
        for (int nb = 0; nb < 8; nb++)
            #pragma unroll
            for (int e = 0; e < 4; e++) oacc[qm][nb][e] = 0.f;

    float suml[2][2] = {};   // cs==0 warps: [qm][g-half]

    for (int kt = 0; kt < NT / TK; kt++) {
        const int slot = kt & 1;
        const int last = (kt == NT / TK - 1);
        if (!last) {
            cpa_k(sbase, kbase, (kt + 1) * TK, slot ^ 1, t);
            cpa_v(sbase, vbase, (kt + 1) * TK, slot ^ 1, t);
        }
        CPA_COMMIT();

        // ---- S partial: 32q x 32k over this warp's 128 channels ----
        const uint32_t kS = sbase + SM_K + (uint32_t)slot * KSLOT;
        float sacc[2][4][4];
        #pragma unroll
        for (int qm = 0; qm < 2; qm++)
            #pragma unroll
            for (int nb = 0; nb < 4; nb++)
                #pragma unroll
                for (int e = 0; e < 4; e++) sacc[qm][nb][e] = 0.f;

        #pragma unroll
        for (int ks2 = 0; ks2 < 8; ks2++) {
            const int ck = cs * 8 + ks2;
            uint32_t a[2][4];
            #pragma unroll
            for (int qm = 0; qm < 2; qm++)
                ldsm_x4(a[qm], sbase + SM_Q +
                        (uint32_t)(((qb + qm * 16 + l16) * QSTR +
                                    ck * 16 + (lane >> 4) * 8) * 2));
            #pragma unroll
            for (int pair = 0; pair < 2; pair++) {
                uint32_t bf[4];
                ldsm_x4(bf, kS + (uint32_t)(((cb + pair * 16 + (lane >> 4) * 8 + (lane & 7)) * QSTR +
                                             ck * 16 + ((lane >> 3) & 1) * 8) * 2));
                #pragma unroll
                for (int qm = 0; qm < 2; qm++) {
                    mma16816(sacc[qm][pair * 2],     a[qm], bf);
                    mma16816(sacc[qm][pair * 2 + 1], a[qm], bf + 2);
                }
            }
        }

        // cs=1 warps publish fp16 partials into the P buffer slots
        __half* P = (__half*)(smem + SM_P);
        if (cs) {
            #pragma unroll
            for (int qm = 0; qm < 2; qm++) {
                const int ra = qb + qm * 16 + g, rb = ra + 8;
                #pragma unroll
                for (int nb = 0; nb < 4; nb++) {
                    const int col = cb + nb * 8 + t4 * 2;
                    *(__half2*)(P + ra * PSTR + col) =
                        __floats2half2_rn(sacc[qm][nb][0], sacc[qm][nb][1]);
                    *(__half2*)(P + rb * PSTR + col) =
                        __floats2half2_rn(sacc[qm][nb][2], sacc[qm][nb][3]);
                }
            }
        }
        BAR_Q(quarter);   // #1: partials ready (this quarter only)

        // cs=0 warps: combine + exp2 entirely in fp16x2, overwrite P in place
        if (!cs) {
            #pragma unroll
            for (int qm = 0; qm < 2; qm++) {
                const int ra = qb + qm * 16 + g, rb = ra + 8;
                __half2 hs0 = __float2half2_rn(0.f);
                __half2 hs1 = __float2half2_rn(0.f);
                #pragma unroll
                for (int nb = 0; nb < 4; nb++) {
                    const int col = cb + nb * 8 + t4 * 2;
                    __half2 xa = *(__half2*)(P + ra * PSTR + col);
                    __half2 xb = *(__half2*)(P + rb * PSTR + col);
                    __half2 sa = __floats2half2_rn(sacc[qm][nb][0], sacc[qm][nb][1]);
                    __half2 sb = __floats2half2_rn(sacc[qm][nb][2], sacc[qm][nb][3]);
                    __half2 ea = h2ex2(__hadd2(sa, xa));
                    __half2 eb = h2ex2(__hadd2(sb, xb));
                    *(__half2*)(P + ra * PSTR + col) = ea;
                    *(__half2*)(P + rb * PSTR + col) = eb;
                    hs0 = __hadd2(hs0, ea);
                    hs1 = __hadd2(hs1, eb);
                }
                float2 f0 = __half22float2(hs0);
                float2 f1 = __half22float2(hs1);
                suml[qm][0] += f0.x + f0.y;
                suml[qm][1] += f1.x + f1.y;
            }
        }
        BAR_Q(quarter);   // #2: P ready (this quarter only)

        // ---- PV: O[32 q of this quarter][64 c per warp] += P[32][64] V[64][64] ----
        const uint32_t vS = sbase + SM_V + (uint32_t)slot * VSLOT;
        #pragma unroll
        for (int ks2 = 0; ks2 < 4; ks2++) {
            uint32_t aP[2][4];
            #pragma unroll
            for (int qm = 0; qm < 2; qm++)
                ldsm_x4(aP[qm], sbase + SM_P +
                        (uint32_t)(((qb + qm * 16 + l16) * PSTR +
                                    ks2 * 16 + (lane >> 4) * 8) * 2));
            #pragma unroll
            for (int pair = 0; pair < 4; pair++) {
                uint32_t bf[4];
                ldsm_x4_t(bf, vS + (uint32_t)(((ks2 * 16 + l16) * QSTR +
                                               cw + pair * 16 + (lane >> 4) * 8) * 2));
                #pragma unroll
                for (int qm = 0; qm < 2; qm++) {
                    mma16816(oacc[qm][pair * 2],     aP[qm], bf);
                    mma16816(oacc[qm][pair * 2 + 1], aP[qm], bf + 2);
                }
            }
        }
        CPA_WAIT0();
        __syncthreads();   // rotate K/V slots (only full barrier per tile)
    }

    // final row-sum reduction (cs==0 warps, partials indexed by kg)
    #pragma unroll
    for (int qm = 0; qm < 2; qm++)
        #pragma unroll
        for (int h = 0; h < 2; h++) {
            suml[qm][h] += __shfl_xor_sync(0xffffffffu, suml[qm][h], 1);
            suml[qm][h] += __shfl_xor_sync(0xffffffffu, suml[qm][h], 2);
        }
    if (!cs && t4 == 0) {
        #pragma unroll
        for (int qm = 0; qm < 2; qm++) {
            psum[kg * 128 + qb + qm * 16 + g]     = suml[qm][0];
            psum[kg * 128 + qb + qm * 16 + g + 8] = suml[qm][1];
        }
    }
    __syncthreads();

    // normalize + stage O^T [c][q] (fp32 [256][132]), coalesced store
    {
        float* sf = (float*)smem;
        float inv0[2], inv1[2];
        #pragma unroll
        for (int qm = 0; qm < 2; qm++) {
            const int ra = qb + qm * 16 + g, rb = ra + 8;
            inv0[qm] = 1.f / (psum[ra] + psum[128 + ra]);
            inv1[qm] = 1.f / (psum[rb] + psum[128 + rb]);
        }
        __syncthreads();
        #pragma unroll
        for (int qm = 0; qm < 2; qm++) {
            const int ra = qb + qm * 16 + g, rb = ra + 8;
            #pragma unroll
            for (int nb = 0; nb < 8; nb++) {
                const int col = cw + nb * 8 + t4 * 2;
                sf[col * 132 + ra]       = oacc[qm][nb][0] * inv0[qm];
                sf[(col + 1) * 132 + ra] = oacc[qm][nb][1] * inv0[qm];
                sf[col * 132 + rb]       = oacc[qm][nb][2] * inv1[qm];
                sf[(col + 1) * 132 + rb] = oacc[qm][nb][3] * inv1[qm];
            }
        }
        __syncthreads();
        float* obase = gout + (size_t)b * CC * NT + i0;
        #pragma unroll
        for (int pass = 0; pass < 2; pass++) {
            const int c = (t >> 2) + pass * 128;
            const int q0 = (t & 3) * 32;
            #pragma unroll
            for (int i = 0; i < 8; i++)
                *(float4*)&obase[(size_t)c * NT + q0 + i * 4] =
                    *(float4*)&sf[c * 132 + q0 + i * 4];
        }
    }
}

extern "C" void kernel_launch(void* const* d_in, const int* in_sizes, int n_in,
                              void* d_out, int out_size)
{
    const float* x  = (const float*)d_in[0];
    const float* mo = (const float*)d_in[1];
    const float* wq = (const float*)d_in[2];
    const float* bq = (const float*)d_in[3];
    const float* wk = (const float*)d_in[4];
    const float* bk = (const float*)d_in[5];
    const float* wv = (const float*)d_in[6];
    const float* bv = (const float*)d_in[7];
    float* out = (float*)d_out;

    cudaFuncSetAttribute(qkv_kernel, cudaFuncAttributeMaxDynamicSharedMemorySize,
                         (int)QK_SMEM);
    dim3 g1(NT / 256, 1, BB * 3);
    qkv_kernel<<<g1, 256, QK_SMEM>>>(x, mo, wq, bq, wk, bk, wv, bv);

    cudaFuncSetAttribute(attn_kernel, cudaFuncAttributeMaxDynamicSharedMemorySize,
                         (int)SMEM_BYTES);
    dim3 g2(NT / TQ, BB);
    attn_kernel<<<g2, 512, SMEM_BYTES>>>(out);
}